// round 11
// baseline (speedup 1.0000x reference)
#include <cuda_runtime.h>
#include <cuda_bf16.h>
#include <cuda_fp16.h>
#include <stdint.h>
#include <stddef.h>

#define DD 128
#define NMAX 50176
#define EMAX 409600

// ---------------- device scratch ----------------
__device__ float g_qa[NMAX * DD];
__device__ float g_qb[NMAX * DD];
__device__ __half g_wtp[NMAX * DD];     // fp16 messages
__device__ __half g_wxp[NMAX * DD];
__device__ __nv_bfloat16 g_ka16[NMAX * DD];
__device__ __nv_bfloat16 g_kb16[NMAX * DD];
__device__ __half g_wh[6 * DD * DD];    // fp16-rounded weights
__device__ int   g_deg[NMAX];           // zero-init at load; re-zeroed by scan1
__device__ int   g_off[NMAX + 1];
__device__ int   g_cur[NMAX];
__device__ int   g_scol[EMAX];
__device__ int   g_bsum[64];

// ---------------- cp.async helpers (portable, Ampere+) ----------------
__device__ __forceinline__ void cp_async16(uint32_t dst_smem, const void* src) {
    asm volatile("cp.async.cg.shared.global [%0], [%1], 16;" ::
                 "r"(dst_smem), "l"(src) : "memory");
}
#define CP_ASYNC_COMMIT() asm volatile("cp.async.commit_group;" ::: "memory")
#define CP_ASYNC_WAIT_ALL() asm volatile("cp.async.wait_group 0;" ::: "memory")

// ---------------- fp16 warp MMA (m16n8k16) ----------------
__device__ __forceinline__ void mma_f16(float* c, uint32_t a0, uint32_t a1,
                                        uint32_t a2, uint32_t a3,
                                        uint32_t b0, uint32_t b1) {
    asm volatile(
        "mma.sync.aligned.m16n8k16.row.col.f32.f16.f16.f32 "
        "{%0,%1,%2,%3}, {%4,%5,%6,%7}, {%8,%9}, {%0,%1,%2,%3};"
        : "+f"(c[0]), "+f"(c[1]), "+f"(c[2]), "+f"(c[3])
        : "r"(a0), "r"(a1), "r"(a2), "r"(a3), "r"(b0), "r"(b1));
}

// smem layout (fp16 elems): Ah[64][136], Al[64][136], B0[128][136], B1[128][136]
#define ROWE 136
#define AH_OFF 0
#define AL_OFF (64 * ROWE)
#define B0_OFF (2 * 64 * ROWE)
#define B1_OFF (B0_OFF + 128 * ROWE)
#define SMEM_ELEMS (B1_OFF + 128 * ROWE)
#define SMEM_BYTES (SMEM_ELEMS * 2)

// ---------------- weight fp16 round ----------------
__global__ void wsplit_kernel(const float* __restrict__ W0,
                              const float* __restrict__ W1,
                              const float* __restrict__ W2,
                              const float* __restrict__ W3,
                              const float* __restrict__ W4,
                              const float* __restrict__ W5) {
    const float* W;
    switch (blockIdx.x) {
        case 0: W = W0; break;
        case 1: W = W1; break;
        case 2: W = W2; break;
        case 3: W = W3; break;
        case 4: W = W4; break;
        default: W = W5; break;
    }
    __half* dst = g_wh + blockIdx.x * (DD * DD);
    for (int i = threadIdx.x; i < DD * DD; i += 256)
        dst[i] = __float2half_rn(W[i]);
}

// ---------------- GEMM inner pass: acc += A(16 rows) @ B(64 cols)^T ----------------
__device__ __forceinline__ void gemm_pass(float acc[8][4], const __half* Abase,
                                          const __half* Bbase, int warpM,
                                          int warpN, int g, int tg) {
    const __half* Ap = Abase + (warpM + g) * ROWE + 2 * tg;
    const __half* Bp = Bbase + (warpN + g) * ROWE + 2 * tg;
#pragma unroll
    for (int ks = 0; ks < 8; ks++) {
        const int k0 = ks * 16;
        uint32_t a0 = *(const uint32_t*)(Ap + k0);
        uint32_t a1 = *(const uint32_t*)(Ap + 8 * ROWE + k0);
        uint32_t a2 = *(const uint32_t*)(Ap + k0 + 8);
        uint32_t a3 = *(const uint32_t*)(Ap + 8 * ROWE + k0 + 8);
#pragma unroll
        for (int fn = 0; fn < 8; fn++) {
            const __half* bp = Bp + fn * 8 * ROWE + k0;
            uint32_t b0 = *(const uint32_t*)bp;
            uint32_t b1 = *(const uint32_t*)(bp + 8);
            mma_f16(acc[fn], a0, a1, a2, a3, b0, b1);
        }
    }
}

// ---------------- fused fp16 projection GEMM ----------------
// grid (ceil(N/64), 2). y=0: t -> {qa, ka16, wtp}; y=1: x -> {qb, kb16, wxp}.
// q: Ah*Wq. k: Ah*Wk. message: Ah*Wm + Al*Wm (A-compensated).
__global__ void __launch_bounds__(256, 2)
proj_mma_kernel(const float* __restrict__ x, const float* __restrict__ t,
                const float* __restrict__ Qa_b, const float* __restrict__ Ka_b,
                const float* __restrict__ Qb_b, const float* __restrict__ Kb_b, int N) {
    extern __shared__ __half sm[];
    uint32_t sm_base = (uint32_t)__cvta_generic_to_shared(sm);

    const int tid  = threadIdx.x;
    const int wid  = tid >> 5;
    const int lane = tid & 31;
    const int y    = blockIdx.y;
    const int row0 = blockIdx.x * 64;

    const float* in = y ? x : t;
    const float* Bias[2];
    Bias[0] = y ? Qb_b : Qa_b;
    Bias[1] = y ? Kb_b : Ka_b;
    float* dst_q = y ? g_qb : g_qa;
    __half* dst_w = y ? g_wxp : g_wtp;
    __nv_bfloat16* dst_k = y ? g_kb16 : g_ka16;
    const __half* wb = g_wh + (size_t)(y * 3) * (DD * DD);

    // ---- issue B0 <- W[0] ----
#pragma unroll
    for (int it = 0; it < 8; it++) {
        int c = tid + it * 256;
        int r = c >> 4, h8 = c & 15;
        uint32_t dst = sm_base + (uint32_t)((B0_OFF + r * ROWE + h8 * 8) * 2);
        cp_async16(dst, wb + (size_t)r * DD + h8 * 8);
    }
    CP_ASYNC_COMMIT();

    // ---- load A tile (64 x 128 fp32), split into Ah/Al fp16 ----
#pragma unroll
    for (int it = 0; it < 8; it++) {
        int c = tid + it * 256;
        int r = c >> 5, q4 = c & 31;
        int gr = row0 + r;
        float4 v = make_float4(0.f, 0.f, 0.f, 0.f);
        if (gr < N) v = *(const float4*)(in + (size_t)gr * DD + q4 * 4);
        __half h0 = __float2half_rn(v.x);
        __half h1 = __float2half_rn(v.y);
        __half h2 = __float2half_rn(v.z);
        __half h3 = __float2half_rn(v.w);
        __half l0 = __float2half_rn(v.x - __half2float(h0));
        __half l1 = __float2half_rn(v.y - __half2float(h1));
        __half l2 = __float2half_rn(v.z - __half2float(h2));
        __half l3 = __float2half_rn(v.w - __half2float(h3));
        __half* ah = sm + AH_OFF + r * ROWE + q4 * 4;
        __half* al = sm + AL_OFF + r * ROWE + q4 * 4;
        ah[0] = h0; ah[1] = h1; ah[2] = h2; ah[3] = h3;
        al[0] = l0; al[1] = l1; al[2] = l2; al[3] = l3;
    }
    CP_ASYNC_WAIT_ALL();
    __syncthreads();

    const int warpM = (wid >> 1) * 16;   // 0,16,32,48
    const int warpN = (wid & 1) * 64;    // 0,64
    const int g = lane >> 2;             // 0..7
    const int tg = lane & 3;             // 0..3
    const __half* Ahs = sm + AH_OFF;
    const __half* Als = sm + AL_OFF;
    const __half* Bs0 = sm + B0_OFF;
    const __half* Bs1 = sm + B1_OFF;

    // ---- prefetch B1 <- W[1], compute q on B0 ----
#pragma unroll
    for (int it = 0; it < 8; it++) {
        int c = tid + it * 256;
        int r = c >> 4, h8 = c & 15;
        uint32_t dst = sm_base + (uint32_t)((B1_OFF + r * ROWE + h8 * 8) * 2);
        cp_async16(dst, wb + (size_t)DD * DD + (size_t)r * DD + h8 * 8);
    }
    CP_ASYNC_COMMIT();

    float acc[8][4];
#pragma unroll
    for (int fn = 0; fn < 8; fn++)
#pragma unroll
        for (int i = 0; i < 4; i++) acc[fn][i] = 0.f;
    gemm_pass(acc, Ahs, Bs0, warpM, warpN, g, tg);

    // epilogue q -> fp32 + bias
    {
        const float* bias = Bias[0];
        int m_lo = row0 + warpM + g, m_hi = m_lo + 8;
#pragma unroll
        for (int fn = 0; fn < 8; fn++) {
            int col = warpN + fn * 8 + 2 * tg;
            float2 bv = *(const float2*)(bias + col);
            if (m_lo < N)
                *(float2*)(dst_q + (size_t)m_lo * DD + col) =
                    make_float2(acc[fn][0] + bv.x, acc[fn][1] + bv.y);
            if (m_hi < N)
                *(float2*)(dst_q + (size_t)m_hi * DD + col) =
                    make_float2(acc[fn][2] + bv.x, acc[fn][3] + bv.y);
        }
    }
    CP_ASYNC_WAIT_ALL();
    __syncthreads();

    // ---- prefetch B0 <- W[2] (message weight), compute k on B1 ----
#pragma unroll
    for (int it = 0; it < 8; it++) {
        int c = tid + it * 256;
        int r = c >> 4, h8 = c & 15;
        uint32_t dst = sm_base + (uint32_t)((B0_OFF + r * ROWE + h8 * 8) * 2);
        cp_async16(dst, wb + (size_t)2 * DD * DD + (size_t)r * DD + h8 * 8);
    }
    CP_ASYNC_COMMIT();

#pragma unroll
    for (int fn = 0; fn < 8; fn++)
#pragma unroll
        for (int i = 0; i < 4; i++) acc[fn][i] = 0.f;
    gemm_pass(acc, Ahs, Bs1, warpM, warpN, g, tg);

    // epilogue k -> bf16 + bias
    {
        const float* bias = Bias[1];
        int m_lo = row0 + warpM + g, m_hi = m_lo + 8;
#pragma unroll
        for (int fn = 0; fn < 8; fn++) {
            int col = warpN + fn * 8 + 2 * tg;
            float2 bv = *(const float2*)(bias + col);
            if (m_lo < N) {
                __nv_bfloat162 h = __floats2bfloat162_rn(acc[fn][0] + bv.x,
                                                         acc[fn][1] + bv.y);
                *(unsigned int*)(dst_k + (size_t)m_lo * DD + col) = *(unsigned int*)&h;
            }
            if (m_hi < N) {
                __nv_bfloat162 h = __floats2bfloat162_rn(acc[fn][2] + bv.x,
                                                         acc[fn][3] + bv.y);
                *(unsigned int*)(dst_k + (size_t)m_hi * DD + col) = *(unsigned int*)&h;
            }
        }
    }
    CP_ASYNC_WAIT_ALL();
    __syncthreads();

    // ---- message GEMM: Ah*Wm + Al*Wm on B0 ----
#pragma unroll
    for (int fn = 0; fn < 8; fn++)
#pragma unroll
        for (int i = 0; i < 4; i++) acc[fn][i] = 0.f;
    gemm_pass(acc, Ahs, Bs0, warpM, warpN, g, tg);
    gemm_pass(acc, Als, Bs0, warpM, warpN, g, tg);

    // epilogue message -> fp16, no bias
    {
        int m_lo = row0 + warpM + g, m_hi = m_lo + 8;
#pragma unroll
        for (int fn = 0; fn < 8; fn++) {
            int col = warpN + fn * 8 + 2 * tg;
            if (m_lo < N) {
                __half2 h = __floats2half2_rn(acc[fn][0], acc[fn][1]);
                *(unsigned int*)(dst_w + (size_t)m_lo * DD + col) = *(unsigned int*)&h;
            }
            if (m_hi < N) {
                __half2 h = __floats2half2_rn(acc[fn][2], acc[fn][3]);
                *(unsigned int*)(dst_w + (size_t)m_hi * DD + col) = *(unsigned int*)&h;
            }
        }
    }
}

// ---------------- CSR construction ----------------
__global__ void count_deg_kernel(const int* __restrict__ rows, int E) {
    int e = blockIdx.x * blockDim.x + threadIdx.x;
    if (e < E) atomicAdd(&g_deg[rows[e]], 1);
}

// scan1 also re-zeroes g_deg for the next call (arrays are zero-init at load)
__global__ void scan1_kernel(int N) {
    __shared__ int wsum[32];
    int tid = threadIdx.x, lane = tid & 31, wid = tid >> 5;
    int i = blockIdx.x * 1024 + tid;
    int v = 0;
    if (i < N) {
        v = g_deg[i];
        g_deg[i] = 0;
    }
    int s = v;
#pragma unroll
    for (int off = 1; off < 32; off <<= 1) {
        int u = __shfl_up_sync(0xffffffffu, s, off);
        if (lane >= off) s += u;
    }
    if (lane == 31) wsum[wid] = s;
    __syncthreads();
    if (wid == 0) {
        int ts = wsum[lane];
#pragma unroll
        for (int off = 1; off < 32; off <<= 1) {
            int u = __shfl_up_sync(0xffffffffu, ts, off);
            if (lane >= off) ts += u;
        }
        wsum[lane] = ts;
    }
    __syncthreads();
    int excl = (wid > 0 ? wsum[wid - 1] : 0) + (s - v);
    if (i < N) g_off[i] = excl;
    if (tid == 1023) g_bsum[blockIdx.x] = wsum[31];
}

// scan3 with inlined block-prefix: warp 0 sums g_bsum[0..blockIdx.x)
__global__ void scan3_kernel(int G, int N, int E) {
    __shared__ int pre_sh;
    int tid = threadIdx.x, lane = tid & 31, wid = tid >> 5;
    if (wid == 0) {
        int b = blockIdx.x;
        int v = 0;
        if (lane < b && lane < G) v += g_bsum[lane];
        if (32 + lane < b && 32 + lane < G) v += g_bsum[32 + lane];
#pragma unroll
        for (int off = 16; off > 0; off >>= 1)
            v += __shfl_xor_sync(0xffffffffu, v, off);
        if (lane == 0) pre_sh = v;
    }
    __syncthreads();
    int pre = pre_sh;
    int i = blockIdx.x * 1024 + tid;
    if (i < N) {
        int o = g_off[i] + pre;
        g_off[i] = o;
        g_cur[i] = o;
    }
    if (blockIdx.x == 0 && tid == 0) g_off[N] = E;
}

__global__ void scatter_kernel(const int* __restrict__ rows, const int* __restrict__ cols,
                               int E) {
    int e = blockIdx.x * blockDim.x + threadIdx.x;
    if (e < E) {
        int p = atomicAdd(&g_cur[rows[e]], 1);
        g_scol[p] = cols[e];
    }
}

// ---------------- fused scores + aggregation: TWO warps per dest node ----------------
// side 0: alpha path (qa . ka -> wt messages -> out_t)
// side 1: beta  path (qb . kb -> wx messages -> out_x)
__global__ void agg_kernel(float* __restrict__ out_x, float* __restrict__ out_t, int N) {
    int gw   = blockIdx.x * (blockDim.x >> 5) + (threadIdx.x >> 5);
    int lane = threadIdx.x & 31;
    int node = gw >> 1;
    int side = gw & 1;
    if (node >= N) return;
    int p0 = g_off[node];
    int p1 = g_off[node + 1];

    const float s = 0.08838834764831845f;  // 1/sqrt(128)
    const float* qsrc = side ? g_qb : g_qa;
    const __nv_bfloat16* ksrc = side ? g_kb16 : g_ka16;
    const __half* wsrc = side ? g_wxp : g_wtp;
    float* out = side ? out_x : out_t;

    float4 q = *(const float4*)(qsrc + (size_t)node * DD + lane * 4);
    q.x *= s; q.y *= s; q.z *= s; q.w *= s;

    float a0 = 0.f, a1 = 0.f, a2 = 0.f, a3 = 0.f;
    float d = 0.f;

    for (int p = p0; p < p1; p++) {
        int j = g_scol[p];
        uint2 ku = *(const uint2*)(ksrc + (size_t)j * DD + lane * 4);
        uint2 wu = *(const uint2*)(wsrc + (size_t)j * DD + lane * 4);

        float2 k0 = __bfloat1622float2(*(__nv_bfloat162*)&ku.x);
        float2 k1 = __bfloat1622float2(*(__nv_bfloat162*)&ku.y);

        float sc = q.x * k0.x + q.y * k0.y + q.z * k1.x + q.w * k1.y;
#pragma unroll
        for (int off = 16; off > 0; off >>= 1)
            sc += __shfl_xor_sync(0xffffffffu, sc, off);
        float e = __expf(sc);

        float2 w0 = __half22float2(*(__half2*)&wu.x);
        float2 w1 = __half22float2(*(__half2*)&wu.y);

        a0 = fmaf(e, w0.x, a0);
        a1 = fmaf(e, w0.y, a1);
        a2 = fmaf(e, w1.x, a2);
        a3 = fmaf(e, w1.y, a3);
        d += e;
    }
    float inv = (d > 0.f) ? 1.f / d : 0.f;
    *(float4*)(out + (size_t)node * DD + lane * 4) =
        make_float4(a0 * inv, a1 * inv, a2 * inv, a3 * inv);
}

// ---------------- launch ----------------
extern "C" void kernel_launch(void* const* d_in, const int* in_sizes, int n_in,
                              void* d_out, int out_size) {
    const float* x    = (const float*)d_in[0];
    const float* t    = (const float*)d_in[1];
    const int*   ei   = (const int*)d_in[2];
    const float* W_x  = (const float*)d_in[3];
    const float* W_t  = (const float*)d_in[4];
    const float* Qa_w = (const float*)d_in[5];
    const float* Qa_b = (const float*)d_in[6];
    const float* Ka_w = (const float*)d_in[7];
    const float* Ka_b = (const float*)d_in[8];
    const float* Qb_w = (const float*)d_in[9];
    const float* Qb_b = (const float*)d_in[10];
    const float* Kb_w = (const float*)d_in[11];
    const float* Kb_b = (const float*)d_in[12];

    const int N = in_sizes[0] / DD;
    const int E = in_sizes[2] / 2;
    const int* rows = ei;
    const int* cols = ei + E;

    float* out_x = (float*)d_out;
    float* out_t = out_x + (size_t)N * DD;

    const int G = (N + 1023) / 1024;

    // weight order: 0=Qa, 1=Ka, 2=W_t, 3=Qb, 4=Kb, 5=W_x
    wsplit_kernel<<<6, 256>>>(Qa_w, Ka_w, W_t, Qb_w, Kb_w, W_x);
    count_deg_kernel<<<(E + 255) / 256, 256>>>(rows, E);
    scan1_kernel<<<G, 1024>>>(N);
    scan3_kernel<<<G, 1024>>>(G, N, E);
    scatter_kernel<<<(E + 255) / 256, 256>>>(rows, cols, E);

    cudaFuncSetAttribute(proj_mma_kernel, cudaFuncAttributeMaxDynamicSharedMemorySize,
                         SMEM_BYTES);
    dim3 pg((N + 63) / 64, 2);
    proj_mma_kernel<<<pg, 256, SMEM_BYTES>>>(x, t, Qa_b, Ka_b, Qb_b, Kb_b, N);

    agg_kernel<<<(2 * N + 7) / 8, 256>>>(out_x, out_t, N);
}

// round 12
// speedup vs baseline: 1.2527x; 1.2527x over previous
#include <cuda_runtime.h>
#include <cuda_bf16.h>
#include <cuda_fp16.h>
#include <stdint.h>
#include <stddef.h>

#define DD 128
#define NMAX 50176
#define EMAX 409600

// ---------------- device scratch ----------------
__device__ float g_qa[NMAX * DD];
__device__ float g_qb[NMAX * DD];
__device__ __half g_wtp[NMAX * DD];     // fp16 messages
__device__ __half g_wxp[NMAX * DD];
__device__ __nv_bfloat16 g_ka16[NMAX * DD];
__device__ __nv_bfloat16 g_kb16[NMAX * DD];
__device__ __half g_wh[6 * DD * DD];    // fp16-rounded weights
__device__ int   g_deg[NMAX];           // zero-init at load; re-zeroed by scan1
__device__ int   g_off[NMAX + 1];
__device__ int   g_cur[NMAX];
__device__ int   g_scol[EMAX];
__device__ int   g_bsum[64];

// ---------------- cp.async helpers (portable, Ampere+) ----------------
__device__ __forceinline__ void cp_async16(uint32_t dst_smem, const void* src) {
    asm volatile("cp.async.cg.shared.global [%0], [%1], 16;" ::
                 "r"(dst_smem), "l"(src) : "memory");
}
#define CP_ASYNC_COMMIT() asm volatile("cp.async.commit_group;" ::: "memory")
#define CP_ASYNC_WAIT_ALL() asm volatile("cp.async.wait_group 0;" ::: "memory")

// ---------------- fp16 warp MMA (m16n8k16) ----------------
__device__ __forceinline__ void mma_f16(float* c, uint32_t a0, uint32_t a1,
                                        uint32_t a2, uint32_t a3,
                                        uint32_t b0, uint32_t b1) {
    asm volatile(
        "mma.sync.aligned.m16n8k16.row.col.f32.f16.f16.f32 "
        "{%0,%1,%2,%3}, {%4,%5,%6,%7}, {%8,%9}, {%0,%1,%2,%3};"
        : "+f"(c[0]), "+f"(c[1]), "+f"(c[2]), "+f"(c[3])
        : "r"(a0), "r"(a1), "r"(a2), "r"(a3), "r"(b0), "r"(b1));
}

// smem layout (fp16 elems): Ah[64][136], Al[64][136], B0[128][136], B1[128][136]
#define ROWE 136
#define AH_OFF 0
#define AL_OFF (64 * ROWE)
#define B0_OFF (2 * 64 * ROWE)
#define B1_OFF (B0_OFF + 128 * ROWE)
#define SMEM_ELEMS (B1_OFF + 128 * ROWE)
#define SMEM_BYTES (SMEM_ELEMS * 2)

// ---------------- fused: weight fp16 round (blocks 0-5) + degree count ----------------
__global__ void wsplit_count_kernel(const float* __restrict__ W0,
                                    const float* __restrict__ W1,
                                    const float* __restrict__ W2,
                                    const float* __restrict__ W3,
                                    const float* __restrict__ W4,
                                    const float* __restrict__ W5,
                                    const int* __restrict__ rows, int E) {
    if (blockIdx.x < 6) {
        const float* W;
        switch (blockIdx.x) {
            case 0: W = W0; break;
            case 1: W = W1; break;
            case 2: W = W2; break;
            case 3: W = W3; break;
            case 4: W = W4; break;
            default: W = W5; break;
        }
        __half* dst = g_wh + blockIdx.x * (DD * DD);
        for (int i = threadIdx.x; i < DD * DD; i += 256)
            dst[i] = __float2half_rn(W[i]);
    } else {
        int e = (blockIdx.x - 6) * 256 + threadIdx.x;
        if (e < E) atomicAdd(&g_deg[rows[e]], 1);
    }
}

// ---------------- GEMM inner pass: acc += A(16 rows) @ B(64 cols)^T ----------------
__device__ __forceinline__ void gemm_pass(float acc[8][4], const __half* Abase,
                                          const __half* Bbase, int warpM,
                                          int warpN, int g, int tg) {
    const __half* Ap = Abase + (warpM + g) * ROWE + 2 * tg;
    const __half* Bp = Bbase + (warpN + g) * ROWE + 2 * tg;
#pragma unroll
    for (int ks = 0; ks < 8; ks++) {
        const int k0 = ks * 16;
        uint32_t a0 = *(const uint32_t*)(Ap + k0);
        uint32_t a1 = *(const uint32_t*)(Ap + 8 * ROWE + k0);
        uint32_t a2 = *(const uint32_t*)(Ap + k0 + 8);
        uint32_t a3 = *(const uint32_t*)(Ap + 8 * ROWE + k0 + 8);
#pragma unroll
        for (int fn = 0; fn < 8; fn++) {
            const __half* bp = Bp + fn * 8 * ROWE + k0;
            uint32_t b0 = *(const uint32_t*)bp;
            uint32_t b1 = *(const uint32_t*)(bp + 8);
            mma_f16(acc[fn], a0, a1, a2, a3, b0, b1);
        }
    }
}

// ---------------- fused fp16 projection GEMM ----------------
// grid (ceil(N/64), 2). y=0: t -> {qa, ka16, wtp}; y=1: x -> {qb, kb16, wxp}.
// q: Ah*Wq. k: Ah*Wk. message: Ah*Wm + Al*Wm (A-compensated).
__global__ void __launch_bounds__(256, 2)
proj_mma_kernel(const float* __restrict__ x, const float* __restrict__ t,
                const float* __restrict__ Qa_b, const float* __restrict__ Ka_b,
                const float* __restrict__ Qb_b, const float* __restrict__ Kb_b, int N) {
    extern __shared__ __half sm[];
    uint32_t sm_base = (uint32_t)__cvta_generic_to_shared(sm);

    const int tid  = threadIdx.x;
    const int wid  = tid >> 5;
    const int lane = tid & 31;
    const int y    = blockIdx.y;
    const int row0 = blockIdx.x * 64;

    const float* in = y ? x : t;
    const float* Bias[2];
    Bias[0] = y ? Qb_b : Qa_b;
    Bias[1] = y ? Kb_b : Ka_b;
    float* dst_q = y ? g_qb : g_qa;
    __half* dst_w = y ? g_wxp : g_wtp;
    __nv_bfloat16* dst_k = y ? g_kb16 : g_ka16;
    const __half* wb = g_wh + (size_t)(y * 3) * (DD * DD);

    // ---- issue B0 <- W[0] ----
#pragma unroll
    for (int it = 0; it < 8; it++) {
        int c = tid + it * 256;
        int r = c >> 4, h8 = c & 15;
        uint32_t dst = sm_base + (uint32_t)((B0_OFF + r * ROWE + h8 * 8) * 2);
        cp_async16(dst, wb + (size_t)r * DD + h8 * 8);
    }
    CP_ASYNC_COMMIT();

    // ---- load A tile (64 x 128 fp32), split into Ah/Al fp16 ----
#pragma unroll
    for (int it = 0; it < 8; it++) {
        int c = tid + it * 256;
        int r = c >> 5, q4 = c & 31;
        int gr = row0 + r;
        float4 v = make_float4(0.f, 0.f, 0.f, 0.f);
        if (gr < N) v = *(const float4*)(in + (size_t)gr * DD + q4 * 4);
        __half h0 = __float2half_rn(v.x);
        __half h1 = __float2half_rn(v.y);
        __half h2 = __float2half_rn(v.z);
        __half h3 = __float2half_rn(v.w);
        __half l0 = __float2half_rn(v.x - __half2float(h0));
        __half l1 = __float2half_rn(v.y - __half2float(h1));
        __half l2 = __float2half_rn(v.z - __half2float(h2));
        __half l3 = __float2half_rn(v.w - __half2float(h3));
        __half* ah = sm + AH_OFF + r * ROWE + q4 * 4;
        __half* al = sm + AL_OFF + r * ROWE + q4 * 4;
        ah[0] = h0; ah[1] = h1; ah[2] = h2; ah[3] = h3;
        al[0] = l0; al[1] = l1; al[2] = l2; al[3] = l3;
    }
    CP_ASYNC_WAIT_ALL();
    __syncthreads();

    const int warpM = (wid >> 1) * 16;   // 0,16,32,48
    const int warpN = (wid & 1) * 64;    // 0,64
    const int g = lane >> 2;             // 0..7
    const int tg = lane & 3;             // 0..3
    const __half* Ahs = sm + AH_OFF;
    const __half* Als = sm + AL_OFF;
    const __half* Bs0 = sm + B0_OFF;
    const __half* Bs1 = sm + B1_OFF;

    // ---- prefetch B1 <- W[1], compute q on B0 ----
#pragma unroll
    for (int it = 0; it < 8; it++) {
        int c = tid + it * 256;
        int r = c >> 4, h8 = c & 15;
        uint32_t dst = sm_base + (uint32_t)((B1_OFF + r * ROWE + h8 * 8) * 2);
        cp_async16(dst, wb + (size_t)DD * DD + (size_t)r * DD + h8 * 8);
    }
    CP_ASYNC_COMMIT();

    float acc[8][4];
#pragma unroll
    for (int fn = 0; fn < 8; fn++)
#pragma unroll
        for (int i = 0; i < 4; i++) acc[fn][i] = 0.f;
    gemm_pass(acc, Ahs, Bs0, warpM, warpN, g, tg);

    // epilogue q -> fp32 + bias
    {
        const float* bias = Bias[0];
        int m_lo = row0 + warpM + g, m_hi = m_lo + 8;
#pragma unroll
        for (int fn = 0; fn < 8; fn++) {
            int col = warpN + fn * 8 + 2 * tg;
            float2 bv = *(const float2*)(bias + col);
            if (m_lo < N)
                *(float2*)(dst_q + (size_t)m_lo * DD + col) =
                    make_float2(acc[fn][0] + bv.x, acc[fn][1] + bv.y);
            if (m_hi < N)
                *(float2*)(dst_q + (size_t)m_hi * DD + col) =
                    make_float2(acc[fn][2] + bv.x, acc[fn][3] + bv.y);
        }
    }
    CP_ASYNC_WAIT_ALL();
    __syncthreads();

    // ---- prefetch B0 <- W[2] (message weight), compute k on B1 ----
#pragma unroll
    for (int it = 0; it < 8; it++) {
        int c = tid + it * 256;
        int r = c >> 4, h8 = c & 15;
        uint32_t dst = sm_base + (uint32_t)((B0_OFF + r * ROWE + h8 * 8) * 2);
        cp_async16(dst, wb + (size_t)2 * DD * DD + (size_t)r * DD + h8 * 8);
    }
    CP_ASYNC_COMMIT();

#pragma unroll
    for (int fn = 0; fn < 8; fn++)
#pragma unroll
        for (int i = 0; i < 4; i++) acc[fn][i] = 0.f;
    gemm_pass(acc, Ahs, Bs1, warpM, warpN, g, tg);

    // epilogue k -> bf16 + bias
    {
        const float* bias = Bias[1];
        int m_lo = row0 + warpM + g, m_hi = m_lo + 8;
#pragma unroll
        for (int fn = 0; fn < 8; fn++) {
            int col = warpN + fn * 8 + 2 * tg;
            float2 bv = *(const float2*)(bias + col);
            if (m_lo < N) {
                __nv_bfloat162 h = __floats2bfloat162_rn(acc[fn][0] + bv.x,
                                                         acc[fn][1] + bv.y);
                *(unsigned int*)(dst_k + (size_t)m_lo * DD + col) = *(unsigned int*)&h;
            }
            if (m_hi < N) {
                __nv_bfloat162 h = __floats2bfloat162_rn(acc[fn][2] + bv.x,
                                                         acc[fn][3] + bv.y);
                *(unsigned int*)(dst_k + (size_t)m_hi * DD + col) = *(unsigned int*)&h;
            }
        }
    }
    CP_ASYNC_WAIT_ALL();
    __syncthreads();

    // ---- message GEMM: Ah*Wm + Al*Wm on B0 ----
#pragma unroll
    for (int fn = 0; fn < 8; fn++)
#pragma unroll
        for (int i = 0; i < 4; i++) acc[fn][i] = 0.f;
    gemm_pass(acc, Ahs, Bs0, warpM, warpN, g, tg);
    gemm_pass(acc, Als, Bs0, warpM, warpN, g, tg);

    // epilogue message -> fp16, no bias
    {
        int m_lo = row0 + warpM + g, m_hi = m_lo + 8;
#pragma unroll
        for (int fn = 0; fn < 8; fn++) {
            int col = warpN + fn * 8 + 2 * tg;
            if (m_lo < N) {
                __half2 h = __floats2half2_rn(acc[fn][0], acc[fn][1]);
                *(unsigned int*)(dst_w + (size_t)m_lo * DD + col) = *(unsigned int*)&h;
            }
            if (m_hi < N) {
                __half2 h = __floats2half2_rn(acc[fn][2], acc[fn][3]);
                *(unsigned int*)(dst_w + (size_t)m_hi * DD + col) = *(unsigned int*)&h;
            }
        }
    }
}

// ---------------- CSR construction ----------------
// scan1 also re-zeroes g_deg for the next call (arrays are zero-init at load)
__global__ void scan1_kernel(int N) {
    __shared__ int wsum[32];
    int tid = threadIdx.x, lane = tid & 31, wid = tid >> 5;
    int i = blockIdx.x * 1024 + tid;
    int v = 0;
    if (i < N) {
        v = g_deg[i];
        g_deg[i] = 0;
    }
    int s = v;
#pragma unroll
    for (int off = 1; off < 32; off <<= 1) {
        int u = __shfl_up_sync(0xffffffffu, s, off);
        if (lane >= off) s += u;
    }
    if (lane == 31) wsum[wid] = s;
    __syncthreads();
    if (wid == 0) {
        int ts = wsum[lane];
#pragma unroll
        for (int off = 1; off < 32; off <<= 1) {
            int u = __shfl_up_sync(0xffffffffu, ts, off);
            if (lane >= off) ts += u;
        }
        wsum[lane] = ts;
    }
    __syncthreads();
    int excl = (wid > 0 ? wsum[wid - 1] : 0) + (s - v);
    if (i < N) g_off[i] = excl;
    if (tid == 1023) g_bsum[blockIdx.x] = wsum[31];
}

// scan3 with inlined block-prefix: warp 0 sums g_bsum[0..blockIdx.x)
__global__ void scan3_kernel(int G, int N, int E) {
    __shared__ int pre_sh;
    int tid = threadIdx.x, lane = tid & 31, wid = tid >> 5;
    if (wid == 0) {
        int b = blockIdx.x;
        int v = 0;
        if (lane < b && lane < G) v += g_bsum[lane];
        if (32 + lane < b && 32 + lane < G) v += g_bsum[32 + lane];
#pragma unroll
        for (int off = 16; off > 0; off >>= 1)
            v += __shfl_xor_sync(0xffffffffu, v, off);
        if (lane == 0) pre_sh = v;
    }
    __syncthreads();
    int pre = pre_sh;
    int i = blockIdx.x * 1024 + tid;
    if (i < N) {
        int o = g_off[i] + pre;
        g_off[i] = o;
        g_cur[i] = o;
    }
    if (blockIdx.x == 0 && tid == 0) g_off[N] = E;
}

__global__ void scatter_kernel(const int* __restrict__ rows, const int* __restrict__ cols,
                               int E) {
    int e = blockIdx.x * blockDim.x + threadIdx.x;
    if (e < E) {
        int p = atomicAdd(&g_cur[rows[e]], 1);
        g_scol[p] = cols[e];
    }
}

// ---------------- fused scores + aggregation: one warp per dest node ----------------
__global__ void agg_kernel(float* __restrict__ out_x, float* __restrict__ out_t, int N) {
    int w    = blockIdx.x * (blockDim.x >> 5) + (threadIdx.x >> 5);
    int lane = threadIdx.x & 31;
    if (w >= N) return;
    int p0 = g_off[w];
    int p1 = g_off[w + 1];

    const float s = 0.08838834764831845f;  // 1/sqrt(128)
    float4 qa = *(const float4*)(g_qa + (size_t)w * DD + lane * 4);
    float4 qb = *(const float4*)(g_qb + (size_t)w * DD + lane * 4);
    qa.x *= s; qa.y *= s; qa.z *= s; qa.w *= s;
    qb.x *= s; qb.y *= s; qb.z *= s; qb.w *= s;

    float stx = 0.f, sty = 0.f, stz = 0.f, stw = 0.f;
    float sxx = 0.f, sxy = 0.f, sxz = 0.f, sxw = 0.f;
    float da = 0.f, db = 0.f;

    // depth-1 index prefetch: break the scol-load -> payload-address chain
    int j = (p0 < p1) ? g_scol[p0] : 0;
    for (int p = p0; p < p1; p++) {
        int j_next = (p + 1 < p1) ? g_scol[p + 1] : 0;
        uint2 kau = *(const uint2*)(g_ka16 + (size_t)j * DD + lane * 4);
        uint2 kbu = *(const uint2*)(g_kb16 + (size_t)j * DD + lane * 4);
        uint2 wtu = *(const uint2*)(g_wtp + (size_t)j * DD + lane * 4);
        uint2 wxu = *(const uint2*)(g_wxp + (size_t)j * DD + lane * 4);

        float2 ka0 = __bfloat1622float2(*(__nv_bfloat162*)&kau.x);
        float2 ka1 = __bfloat1622float2(*(__nv_bfloat162*)&kau.y);
        float2 kb0 = __bfloat1622float2(*(__nv_bfloat162*)&kbu.x);
        float2 kb1 = __bfloat1622float2(*(__nv_bfloat162*)&kbu.y);

        float sa = qa.x * ka0.x + qa.y * ka0.y + qa.z * ka1.x + qa.w * ka1.y;
        float sb = qb.x * kb0.x + qb.y * kb0.y + qb.z * kb1.x + qb.w * kb1.y;
#pragma unroll
        for (int off = 16; off > 0; off >>= 1) {
            sa += __shfl_xor_sync(0xffffffffu, sa, off);
            sb += __shfl_xor_sync(0xffffffffu, sb, off);
        }
        float ea = __expf(sa);
        float eb = __expf(sb);

        float2 wt0 = __half22float2(*(__half2*)&wtu.x);
        float2 wt1 = __half22float2(*(__half2*)&wtu.y);
        float2 wx0 = __half22float2(*(__half2*)&wxu.x);
        float2 wx1 = __half22float2(*(__half2*)&wxu.y);

        stx = fmaf(ea, wt0.x, stx);
        sty = fmaf(ea, wt0.y, sty);
        stz = fmaf(ea, wt1.x, stz);
        stw = fmaf(ea, wt1.y, stw);
        sxx = fmaf(eb, wx0.x, sxx);
        sxy = fmaf(eb, wx0.y, sxy);
        sxz = fmaf(eb, wx1.x, sxz);
        sxw = fmaf(eb, wx1.y, sxw);
        da += ea;
        db += eb;
        j = j_next;
    }
    float ia = (da > 0.f) ? 1.f / da : 0.f;
    float ib = (db > 0.f) ? 1.f / db : 0.f;
    *(float4*)(out_t + (size_t)w * DD + lane * 4) =
        make_float4(stx * ia, sty * ia, stz * ia, stw * ia);
    *(float4*)(out_x + (size_t)w * DD + lane * 4) =
        make_float4(sxx * ib, sxy * ib, sxz * ib, sxw * ib);
}

// ---------------- launch ----------------
extern "C" void kernel_launch(void* const* d_in, const int* in_sizes, int n_in,
                              void* d_out, int out_size) {
    const float* x    = (const float*)d_in[0];
    const float* t    = (const float*)d_in[1];
    const int*   ei   = (const int*)d_in[2];
    const float* W_x  = (const float*)d_in[3];
    const float* W_t  = (const float*)d_in[4];
    const float* Qa_w = (const float*)d_in[5];
    const float* Qa_b = (const float*)d_in[6];
    const float* Ka_w = (const float*)d_in[7];
    const float* Ka_b = (const float*)d_in[8];
    const float* Qb_w = (const float*)d_in[9];
    const float* Qb_b = (const float*)d_in[10];
    const float* Kb_w = (const float*)d_in[11];
    const float* Kb_b = (const float*)d_in[12];

    const int N = in_sizes[0] / DD;
    const int E = in_sizes[2] / 2;
    const int* rows = ei;
    const int* cols = ei + E;

    float* out_x = (float*)d_out;
    float* out_t = out_x + (size_t)N * DD;

    const int G = (N + 1023) / 1024;

    // weight order: 0=Qa, 1=Ka, 2=W_t, 3=Qb, 4=Kb, 5=W_x
    wsplit_count_kernel<<<6 + (E + 255) / 256, 256>>>(Qa_w, Ka_w, W_t, Qb_w, Kb_w, W_x,
                                                      rows, E);
    scan1_kernel<<<G, 1024>>>(N);
    scan3_kernel<<<G, 1024>>>(G, N, E);
    scatter_kernel<<<(E + 255) / 256, 256>>>(rows, cols, E);

    cudaFuncSetAttribute(proj_mma_kernel, cudaFuncAttributeMaxDynamicSharedMemorySize,
                         SMEM_BYTES);
    dim3 pg((N + 63) / 64, 2);
    proj_mma_kernel<<<pg, 256, SMEM_BYTES>>>(x, t, Qa_b, Ka_b, Qb_b, Kb_b, N);

    agg_kernel<<<(N + 7) / 8, 256>>>(out_x, out_t, N);
}

// round 13
// speedup vs baseline: 1.2915x; 1.0310x over previous
#include <cuda_runtime.h>
#include <cuda_bf16.h>
#include <cuda_fp16.h>
#include <stdint.h>
#include <stddef.h>

#define DD 128
#define NMAX 50176
#define EMAX 409600

// ---------------- device scratch ----------------
__device__ float g_qa[NMAX * DD];
__device__ float g_qb[NMAX * DD];
__device__ __half g_wtp[NMAX * DD];     // fp16 messages
__device__ __half g_wxp[NMAX * DD];
__device__ __nv_bfloat16 g_ka16[NMAX * DD];
__device__ __nv_bfloat16 g_kb16[NMAX * DD];
__device__ __half g_wh[6 * DD * DD];    // fp16-rounded weights
__device__ int   g_deg[NMAX];           // zero-init at load; re-zeroed by scan1
__device__ int   g_off[NMAX + 1];
__device__ int   g_cur[NMAX];
__device__ int   g_scol[EMAX];
__device__ int   g_bsum[64];

// ---------------- cp.async helpers (portable, Ampere+) ----------------
__device__ __forceinline__ void cp_async16(uint32_t dst_smem, const void* src) {
    asm volatile("cp.async.cg.shared.global [%0], [%1], 16;" ::
                 "r"(dst_smem), "l"(src) : "memory");
}
#define CP_ASYNC_COMMIT() asm volatile("cp.async.commit_group;" ::: "memory")
#define CP_ASYNC_WAIT_ALL() asm volatile("cp.async.wait_group 0;" ::: "memory")

// ---------------- fp16 warp MMA (m16n8k16) ----------------
__device__ __forceinline__ void mma_f16(float* c, uint32_t a0, uint32_t a1,
                                        uint32_t a2, uint32_t a3,
                                        uint32_t b0, uint32_t b1) {
    asm volatile(
        "mma.sync.aligned.m16n8k16.row.col.f32.f16.f16.f32 "
        "{%0,%1,%2,%3}, {%4,%5,%6,%7}, {%8,%9}, {%0,%1,%2,%3};"
        : "+f"(c[0]), "+f"(c[1]), "+f"(c[2]), "+f"(c[3])
        : "r"(a0), "r"(a1), "r"(a2), "r"(a3), "r"(b0), "r"(b1));
}

// smem layout (fp16 elems): Ah[64][136], Al[64][136], B0[128][136], B1[128][136]
#define ROWE 136
#define AH_OFF 0
#define AL_OFF (64 * ROWE)
#define B0_OFF (2 * 64 * ROWE)
#define B1_OFF (B0_OFF + 128 * ROWE)
#define SMEM_ELEMS (B1_OFF + 128 * ROWE)
#define SMEM_BYTES (SMEM_ELEMS * 2)

// ---------------- weight fp16 round ----------------
__global__ void wsplit_kernel(const float* __restrict__ W0,
                              const float* __restrict__ W1,
                              const float* __restrict__ W2,
                              const float* __restrict__ W3,
                              const float* __restrict__ W4,
                              const float* __restrict__ W5) {
    const float* W;
    switch (blockIdx.x) {
        case 0: W = W0; break;
        case 1: W = W1; break;
        case 2: W = W2; break;
        case 3: W = W3; break;
        case 4: W = W4; break;
        default: W = W5; break;
    }
    __half* dst = g_wh + blockIdx.x * (DD * DD);
    for (int i = threadIdx.x; i < DD * DD; i += 256)
        dst[i] = __float2half_rn(W[i]);
}

// ---------------- GEMM inner pass: acc += A(16 rows) @ B(64 cols)^T ----------------
__device__ __forceinline__ void gemm_pass(float acc[8][4], const __half* Abase,
                                          const __half* Bbase, int warpM,
                                          int warpN, int g, int tg) {
    const __half* Ap = Abase + (warpM + g) * ROWE + 2 * tg;
    const __half* Bp = Bbase + (warpN + g) * ROWE + 2 * tg;
#pragma unroll
    for (int ks = 0; ks < 8; ks++) {
        const int k0 = ks * 16;
        uint32_t a0 = *(const uint32_t*)(Ap + k0);
        uint32_t a1 = *(const uint32_t*)(Ap + 8 * ROWE + k0);
        uint32_t a2 = *(const uint32_t*)(Ap + k0 + 8);
        uint32_t a3 = *(const uint32_t*)(Ap + 8 * ROWE + k0 + 8);
#pragma unroll
        for (int fn = 0; fn < 8; fn++) {
            const __half* bp = Bp + fn * 8 * ROWE + k0;
            uint32_t b0 = *(const uint32_t*)bp;
            uint32_t b1 = *(const uint32_t*)(bp + 8);
            mma_f16(acc[fn], a0, a1, a2, a3, b0, b1);
        }
    }
}

// ---------------- fused fp16 projection GEMM ----------------
// grid (ceil(N/64), 2). y=0: t -> {qa, ka16, wtp}; y=1: x -> {qb, kb16, wxp}.
// q: Ah*Wq. k: Ah*Wk. message: Ah*Wm + Al*Wm (A-compensated).
__global__ void __launch_bounds__(256, 2)
proj_mma_kernel(const float* __restrict__ x, const float* __restrict__ t,
                const float* __restrict__ Qa_b, const float* __restrict__ Ka_b,
                const float* __restrict__ Qb_b, const float* __restrict__ Kb_b, int N) {
    extern __shared__ __half sm[];
    uint32_t sm_base = (uint32_t)__cvta_generic_to_shared(sm);

    const int tid  = threadIdx.x;
    const int wid  = tid >> 5;
    const int lane = tid & 31;
    const int y    = blockIdx.y;
    const int row0 = blockIdx.x * 64;

    const float* in = y ? x : t;
    const float* Bias[2];
    Bias[0] = y ? Qb_b : Qa_b;
    Bias[1] = y ? Kb_b : Ka_b;
    float* dst_q = y ? g_qb : g_qa;
    __half* dst_w = y ? g_wxp : g_wtp;
    __nv_bfloat16* dst_k = y ? g_kb16 : g_ka16;
    const __half* wb = g_wh + (size_t)(y * 3) * (DD * DD);

    // ---- issue B0 <- W[0] ----
#pragma unroll
    for (int it = 0; it < 8; it++) {
        int c = tid + it * 256;
        int r = c >> 4, h8 = c & 15;
        uint32_t dst = sm_base + (uint32_t)((B0_OFF + r * ROWE + h8 * 8) * 2);
        cp_async16(dst, wb + (size_t)r * DD + h8 * 8);
    }
    CP_ASYNC_COMMIT();

    // ---- load A tile (64 x 128 fp32), split into Ah/Al fp16 ----
#pragma unroll
    for (int it = 0; it < 8; it++) {
        int c = tid + it * 256;
        int r = c >> 5, q4 = c & 31;
        int gr = row0 + r;
        float4 v = make_float4(0.f, 0.f, 0.f, 0.f);
        if (gr < N) v = *(const float4*)(in + (size_t)gr * DD + q4 * 4);
        __half h0 = __float2half_rn(v.x);
        __half h1 = __float2half_rn(v.y);
        __half h2 = __float2half_rn(v.z);
        __half h3 = __float2half_rn(v.w);
        __half l0 = __float2half_rn(v.x - __half2float(h0));
        __half l1 = __float2half_rn(v.y - __half2float(h1));
        __half l2 = __float2half_rn(v.z - __half2float(h2));
        __half l3 = __float2half_rn(v.w - __half2float(h3));
        __half* ah = sm + AH_OFF + r * ROWE + q4 * 4;
        __half* al = sm + AL_OFF + r * ROWE + q4 * 4;
        ah[0] = h0; ah[1] = h1; ah[2] = h2; ah[3] = h3;
        al[0] = l0; al[1] = l1; al[2] = l2; al[3] = l3;
    }
    CP_ASYNC_WAIT_ALL();
    __syncthreads();

    const int warpM = (wid >> 1) * 16;   // 0,16,32,48
    const int warpN = (wid & 1) * 64;    // 0,64
    const int g = lane >> 2;             // 0..7
    const int tg = lane & 3;             // 0..3
    const __half* Ahs = sm + AH_OFF;
    const __half* Als = sm + AL_OFF;
    const __half* Bs0 = sm + B0_OFF;
    const __half* Bs1 = sm + B1_OFF;

    // ---- prefetch B1 <- W[1], compute q on B0 ----
#pragma unroll
    for (int it = 0; it < 8; it++) {
        int c = tid + it * 256;
        int r = c >> 4, h8 = c & 15;
        uint32_t dst = sm_base + (uint32_t)((B1_OFF + r * ROWE + h8 * 8) * 2);
        cp_async16(dst, wb + (size_t)DD * DD + (size_t)r * DD + h8 * 8);
    }
    CP_ASYNC_COMMIT();

    float acc[8][4];
#pragma unroll
    for (int fn = 0; fn < 8; fn++)
#pragma unroll
        for (int i = 0; i < 4; i++) acc[fn][i] = 0.f;
    gemm_pass(acc, Ahs, Bs0, warpM, warpN, g, tg);

    // epilogue q -> fp32 + bias
    {
        const float* bias = Bias[0];
        int m_lo = row0 + warpM + g, m_hi = m_lo + 8;
#pragma unroll
        for (int fn = 0; fn < 8; fn++) {
            int col = warpN + fn * 8 + 2 * tg;
            float2 bv = *(const float2*)(bias + col);
            if (m_lo < N)
                *(float2*)(dst_q + (size_t)m_lo * DD + col) =
                    make_float2(acc[fn][0] + bv.x, acc[fn][1] + bv.y);
            if (m_hi < N)
                *(float2*)(dst_q + (size_t)m_hi * DD + col) =
                    make_float2(acc[fn][2] + bv.x, acc[fn][3] + bv.y);
        }
    }
    CP_ASYNC_WAIT_ALL();
    __syncthreads();

    // ---- prefetch B0 <- W[2] (message weight), compute k on B1 ----
#pragma unroll
    for (int it = 0; it < 8; it++) {
        int c = tid + it * 256;
        int r = c >> 4, h8 = c & 15;
        uint32_t dst = sm_base + (uint32_t)((B0_OFF + r * ROWE + h8 * 8) * 2);
        cp_async16(dst, wb + (size_t)2 * DD * DD + (size_t)r * DD + h8 * 8);
    }
    CP_ASYNC_COMMIT();

#pragma unroll
    for (int fn = 0; fn < 8; fn++)
#pragma unroll
        for (int i = 0; i < 4; i++) acc[fn][i] = 0.f;
    gemm_pass(acc, Ahs, Bs1, warpM, warpN, g, tg);

    // epilogue k -> bf16 + bias
    {
        const float* bias = Bias[1];
        int m_lo = row0 + warpM + g, m_hi = m_lo + 8;
#pragma unroll
        for (int fn = 0; fn < 8; fn++) {
            int col = warpN + fn * 8 + 2 * tg;
            float2 bv = *(const float2*)(bias + col);
            if (m_lo < N) {
                __nv_bfloat162 h = __floats2bfloat162_rn(acc[fn][0] + bv.x,
                                                         acc[fn][1] + bv.y);
                *(unsigned int*)(dst_k + (size_t)m_lo * DD + col) = *(unsigned int*)&h;
            }
            if (m_hi < N) {
                __nv_bfloat162 h = __floats2bfloat162_rn(acc[fn][2] + bv.x,
                                                         acc[fn][3] + bv.y);
                *(unsigned int*)(dst_k + (size_t)m_hi * DD + col) = *(unsigned int*)&h;
            }
        }
    }
    CP_ASYNC_WAIT_ALL();
    __syncthreads();

    // ---- message GEMM: Ah*Wm + Al*Wm on B0 ----
#pragma unroll
    for (int fn = 0; fn < 8; fn++)
#pragma unroll
        for (int i = 0; i < 4; i++) acc[fn][i] = 0.f;
    gemm_pass(acc, Ahs, Bs0, warpM, warpN, g, tg);
    gemm_pass(acc, Als, Bs0, warpM, warpN, g, tg);

    // epilogue message -> fp16, no bias
    {
        int m_lo = row0 + warpM + g, m_hi = m_lo + 8;
#pragma unroll
        for (int fn = 0; fn < 8; fn++) {
            int col = warpN + fn * 8 + 2 * tg;
            if (m_lo < N) {
                __half2 h = __floats2half2_rn(acc[fn][0], acc[fn][1]);
                *(unsigned int*)(dst_w + (size_t)m_lo * DD + col) = *(unsigned int*)&h;
            }
            if (m_hi < N) {
                __half2 h = __floats2half2_rn(acc[fn][2], acc[fn][3]);
                *(unsigned int*)(dst_w + (size_t)m_hi * DD + col) = *(unsigned int*)&h;
            }
        }
    }
}

// ---------------- CSR construction ----------------
__global__ void count_deg_kernel(const int* __restrict__ rows, int E) {
    int e = blockIdx.x * blockDim.x + threadIdx.x;
    if (e < E) atomicAdd(&g_deg[rows[e]], 1);
}

// scan1 also re-zeroes g_deg for the next call (arrays are zero-init at load)
__global__ void scan1_kernel(int N) {
    __shared__ int wsum[32];
    int tid = threadIdx.x, lane = tid & 31, wid = tid >> 5;
    int i = blockIdx.x * 1024 + tid;
    int v = 0;
    if (i < N) {
        v = g_deg[i];
        g_deg[i] = 0;
    }
    int s = v;
#pragma unroll
    for (int off = 1; off < 32; off <<= 1) {
        int u = __shfl_up_sync(0xffffffffu, s, off);
        if (lane >= off) s += u;
    }
    if (lane == 31) wsum[wid] = s;
    __syncthreads();
    if (wid == 0) {
        int ts = wsum[lane];
#pragma unroll
        for (int off = 1; off < 32; off <<= 1) {
            int u = __shfl_up_sync(0xffffffffu, ts, off);
            if (lane >= off) ts += u;
        }
        wsum[lane] = ts;
    }
    __syncthreads();
    int excl = (wid > 0 ? wsum[wid - 1] : 0) + (s - v);
    if (i < N) g_off[i] = excl;
    if (tid == 1023) g_bsum[blockIdx.x] = wsum[31];
}

// scan3 with inlined block-prefix: warp 0 sums g_bsum[0..blockIdx.x)
__global__ void scan3_kernel(int G, int N, int E) {
    __shared__ int pre_sh;
    int tid = threadIdx.x, lane = tid & 31, wid = tid >> 5;
    if (wid == 0) {
        int b = blockIdx.x;
        int v = 0;
        if (lane < b && lane < G) v += g_bsum[lane];
        if (32 + lane < b && 32 + lane < G) v += g_bsum[32 + lane];
#pragma unroll
        for (int off = 16; off > 0; off >>= 1)
            v += __shfl_xor_sync(0xffffffffu, v, off);
        if (lane == 0) pre_sh = v;
    }
    __syncthreads();
    int pre = pre_sh;
    int i = blockIdx.x * 1024 + tid;
    if (i < N) {
        int o = g_off[i] + pre;
        g_off[i] = o;
        g_cur[i] = o;
    }
    if (blockIdx.x == 0 && tid == 0) g_off[N] = E;
}

__global__ void scatter_kernel(const int* __restrict__ rows, const int* __restrict__ cols,
                               int E) {
    int e = blockIdx.x * blockDim.x + threadIdx.x;
    if (e < E) {
        int p = atomicAdd(&g_cur[rows[e]], 1);
        g_scol[p] = cols[e];
    }
}

// ---------------- fused scores + aggregation: one warp per dest node ----------------
__global__ void agg_kernel(float* __restrict__ out_x, float* __restrict__ out_t, int N) {
    int w    = blockIdx.x * (blockDim.x >> 5) + (threadIdx.x >> 5);
    int lane = threadIdx.x & 31;
    if (w >= N) return;
    int p0 = g_off[w];
    int p1 = g_off[w + 1];

    const float s = 0.08838834764831845f;  // 1/sqrt(128)
    float4 qa = *(const float4*)(g_qa + (size_t)w * DD + lane * 4);
    float4 qb = *(const float4*)(g_qb + (size_t)w * DD + lane * 4);
    qa.x *= s; qa.y *= s; qa.z *= s; qa.w *= s;
    qb.x *= s; qb.y *= s; qb.z *= s; qb.w *= s;

    float stx = 0.f, sty = 0.f, stz = 0.f, stw = 0.f;
    float sxx = 0.f, sxy = 0.f, sxz = 0.f, sxw = 0.f;
    float da = 0.f, db = 0.f;

    // depth-1 index prefetch: break the scol-load -> payload-address chain
    int j = (p0 < p1) ? g_scol[p0] : 0;
    for (int p = p0; p < p1; p++) {
        int j_next = (p + 1 < p1) ? g_scol[p + 1] : 0;
        uint2 kau = *(const uint2*)(g_ka16 + (size_t)j * DD + lane * 4);
        uint2 kbu = *(const uint2*)(g_kb16 + (size_t)j * DD + lane * 4);
        uint2 wtu = *(const uint2*)(g_wtp + (size_t)j * DD + lane * 4);
        uint2 wxu = *(const uint2*)(g_wxp + (size_t)j * DD + lane * 4);

        float2 ka0 = __bfloat1622float2(*(__nv_bfloat162*)&kau.x);
        float2 ka1 = __bfloat1622float2(*(__nv_bfloat162*)&kau.y);
        float2 kb0 = __bfloat1622float2(*(__nv_bfloat162*)&kbu.x);
        float2 kb1 = __bfloat1622float2(*(__nv_bfloat162*)&kbu.y);

        float sa = qa.x * ka0.x + qa.y * ka0.y + qa.z * ka1.x + qa.w * ka1.y;
        float sb = qb.x * kb0.x + qb.y * kb0.y + qb.z * kb1.x + qb.w * kb1.y;
#pragma unroll
        for (int off = 16; off > 0; off >>= 1) {
            sa += __shfl_xor_sync(0xffffffffu, sa, off);
            sb += __shfl_xor_sync(0xffffffffu, sb, off);
        }
        float ea = __expf(sa);
        float eb = __expf(sb);

        float2 wt0 = __half22float2(*(__half2*)&wtu.x);
        float2 wt1 = __half22float2(*(__half2*)&wtu.y);
        float2 wx0 = __half22float2(*(__half2*)&wxu.x);
        float2 wx1 = __half22float2(*(__half2*)&wxu.y);

        stx = fmaf(ea, wt0.x, stx);
        sty = fmaf(ea, wt0.y, sty);
        stz = fmaf(ea, wt1.x, stz);
        stw = fmaf(ea, wt1.y, stw);
        sxx = fmaf(eb, wx0.x, sxx);
        sxy = fmaf(eb, wx0.y, sxy);
        sxz = fmaf(eb, wx1.x, sxz);
        sxw = fmaf(eb, wx1.y, sxw);
        da += ea;
        db += eb;
        j = j_next;
    }
    float ia = (da > 0.f) ? 1.f / da : 0.f;
    float ib = (db > 0.f) ? 1.f / db : 0.f;
    *(float4*)(out_t + (size_t)w * DD + lane * 4) =
        make_float4(stx * ia, sty * ia, stz * ia, stw * ia);
    *(float4*)(out_x + (size_t)w * DD + lane * 4) =
        make_float4(sxx * ib, sxy * ib, sxz * ib, sxw * ib);
}

// ---------------- launch (fork-join: CSR chain overlaps proj GEMMs) ----------------
static cudaStream_t g_s2 = nullptr;
static cudaEvent_t g_ev0 = nullptr, g_ev1 = nullptr;
static bool g_init_done = false;
static bool g_overlap_ok = false;

extern "C" void kernel_launch(void* const* d_in, const int* in_sizes, int n_in,
                              void* d_out, int out_size) {
    const float* x    = (const float*)d_in[0];
    const float* t    = (const float*)d_in[1];
    const int*   ei   = (const int*)d_in[2];
    const float* W_x  = (const float*)d_in[3];
    const float* W_t  = (const float*)d_in[4];
    const float* Qa_w = (const float*)d_in[5];
    const float* Qa_b = (const float*)d_in[6];
    const float* Ka_w = (const float*)d_in[7];
    const float* Ka_b = (const float*)d_in[8];
    const float* Qb_w = (const float*)d_in[9];
    const float* Qb_b = (const float*)d_in[10];
    const float* Kb_w = (const float*)d_in[11];
    const float* Kb_b = (const float*)d_in[12];

    const int N = in_sizes[0] / DD;
    const int E = in_sizes[2] / 2;
    const int* rows = ei;
    const int* cols = ei + E;

    float* out_x = (float*)d_out;
    float* out_t = out_x + (size_t)N * DD;

    const int G = (N + 1023) / 1024;

    if (!g_init_done) {
        g_init_done = true;
        bool ok = (cudaStreamCreateWithFlags(&g_s2, cudaStreamNonBlocking) == cudaSuccess);
        ok = ok && (cudaEventCreateWithFlags(&g_ev0, cudaEventDisableTiming) == cudaSuccess);
        ok = ok && (cudaEventCreateWithFlags(&g_ev1, cudaEventDisableTiming) == cudaSuccess);
        g_overlap_ok = ok;
    }

    cudaFuncSetAttribute(proj_mma_kernel, cudaFuncAttributeMaxDynamicSharedMemorySize,
                         SMEM_BYTES);
    dim3 pg((N + 63) / 64, 2);

    if (g_overlap_ok) {
        // fork: CSR chain on g_s2, weights+proj on the main stream
        cudaEventRecord(g_ev0, 0);
        cudaStreamWaitEvent(g_s2, g_ev0, 0);

        count_deg_kernel<<<(E + 255) / 256, 256, 0, g_s2>>>(rows, E);
        scan1_kernel<<<G, 1024, 0, g_s2>>>(N);
        scan3_kernel<<<G, 1024, 0, g_s2>>>(G, N, E);
        scatter_kernel<<<(E + 255) / 256, 256, 0, g_s2>>>(rows, cols, E);
        cudaEventRecord(g_ev1, g_s2);

        // weight order: 0=Qa, 1=Ka, 2=W_t, 3=Qb, 4=Kb, 5=W_x
        wsplit_kernel<<<6, 256>>>(Qa_w, Ka_w, W_t, Qb_w, Kb_w, W_x);
        proj_mma_kernel<<<pg, 256, SMEM_BYTES>>>(x, t, Qa_b, Ka_b, Qb_b, Kb_b, N);

        // join: agg needs both proj (program order) and CSR (event)
        cudaStreamWaitEvent(0, g_ev1, 0);
        agg_kernel<<<(N + 7) / 8, 256>>>(out_x, out_t, N);
    } else {
        wsplit_kernel<<<6, 256>>>(Qa_w, Ka_w, W_t, Qb_w, Kb_w, W_x);
        count_deg_kernel<<<(E + 255) / 256, 256>>>(rows, E);
        scan1_kernel<<<G, 1024>>>(N);
        scan3_kernel<<<G, 1024>>>(G, N, E);
        scatter_kernel<<<(E + 255) / 256, 256>>>(rows, cols, E);
        proj_mma_kernel<<<pg, 256, SMEM_BYTES>>>(x, t, Qa_b, Ka_b, Qb_b, Kb_b, N);
        agg_kernel<<<(N + 7) / 8, 256>>>(out_x, out_t, N);
    }
}

// round 14
// speedup vs baseline: 1.3909x; 1.0770x over previous
#include <cuda_runtime.h>
#include <cuda_bf16.h>
#include <cuda_fp16.h>
#include <stdint.h>
#include <stddef.h>

#define DD 128
#define NMAX 50176
#define EMAX 409600

// ---------------- device scratch ----------------
__device__ float g_qa[NMAX * DD];
__device__ float g_qb[NMAX * DD];
__device__ __half g_wtp[NMAX * DD];     // fp16 messages
__device__ __half g_wxp[NMAX * DD];
__device__ __nv_bfloat16 g_ka16[NMAX * DD];
__device__ __nv_bfloat16 g_kb16[NMAX * DD];
__device__ __half g_wh[6 * DD * DD];    // fp16-rounded weights
__device__ int   g_deg[NMAX];           // zero-init at load; re-zeroed by scan1
__device__ int   g_off[NMAX + 1];
__device__ int   g_cur[NMAX];
__device__ int   g_scol[EMAX];
__device__ int   g_bsum[64];

// ---------------- cp.async helpers (portable, Ampere+) ----------------
__device__ __forceinline__ void cp_async16(uint32_t dst_smem, const void* src) {
    asm volatile("cp.async.cg.shared.global [%0], [%1], 16;" ::
                 "r"(dst_smem), "l"(src) : "memory");
}
#define CP_ASYNC_COMMIT() asm volatile("cp.async.commit_group;" ::: "memory")
#define CP_ASYNC_WAIT_ALL() asm volatile("cp.async.wait_group 0;" ::: "memory")

// ---------------- fp16 warp MMA (m16n8k16) ----------------
__device__ __forceinline__ void mma_f16(float* c, uint32_t a0, uint32_t a1,
                                        uint32_t a2, uint32_t a3,
                                        uint32_t b0, uint32_t b1) {
    asm volatile(
        "mma.sync.aligned.m16n8k16.row.col.f32.f16.f16.f32 "
        "{%0,%1,%2,%3}, {%4,%5,%6,%7}, {%8,%9}, {%0,%1,%2,%3};"
        : "+f"(c[0]), "+f"(c[1]), "+f"(c[2]), "+f"(c[3])
        : "r"(a0), "r"(a1), "r"(a2), "r"(a3), "r"(b0), "r"(b1));
}

// smem layout (fp16 elems): Ah[64][136], B0[128][136], B1[128][136]
#define ROWE 136
#define AH_OFF 0
#define B0_OFF (64 * ROWE)
#define B1_OFF (B0_OFF + 128 * ROWE)
#define SMEM_ELEMS (B1_OFF + 128 * ROWE)
#define SMEM_BYTES (SMEM_ELEMS * 2)

// ---------------- weight fp16 round ----------------
__global__ void wsplit_kernel(const float* __restrict__ W0,
                              const float* __restrict__ W1,
                              const float* __restrict__ W2,
                              const float* __restrict__ W3,
                              const float* __restrict__ W4,
                              const float* __restrict__ W5) {
    const float* W;
    switch (blockIdx.x) {
        case 0: W = W0; break;
        case 1: W = W1; break;
        case 2: W = W2; break;
        case 3: W = W3; break;
        case 4: W = W4; break;
        default: W = W5; break;
    }
    __half* dst = g_wh + blockIdx.x * (DD * DD);
    for (int i = threadIdx.x; i < DD * DD; i += 256)
        dst[i] = __float2half_rn(W[i]);
}

// ---------------- GEMM inner pass: acc += A(16 rows) @ B(64 cols)^T ----------------
__device__ __forceinline__ void gemm_pass(float acc[8][4], const __half* Abase,
                                          const __half* Bbase, int warpM,
                                          int warpN, int g, int tg) {
    const __half* Ap = Abase + (warpM + g) * ROWE + 2 * tg;
    const __half* Bp = Bbase + (warpN + g) * ROWE + 2 * tg;
#pragma unroll
    for (int ks = 0; ks < 8; ks++) {
        const int k0 = ks * 16;
        uint32_t a0 = *(const uint32_t*)(Ap + k0);
        uint32_t a1 = *(const uint32_t*)(Ap + 8 * ROWE + k0);
        uint32_t a2 = *(const uint32_t*)(Ap + k0 + 8);
        uint32_t a3 = *(const uint32_t*)(Ap + 8 * ROWE + k0 + 8);
#pragma unroll
        for (int fn = 0; fn < 8; fn++) {
            const __half* bp = Bp + fn * 8 * ROWE + k0;
            uint32_t b0 = *(const uint32_t*)bp;
            uint32_t b1 = *(const uint32_t*)(bp + 8);
            mma_f16(acc[fn], a0, a1, a2, a3, b0, b1);
        }
    }
}

// ---------------- fused fp16 projection GEMM ----------------
// grid (ceil(N/64), 2). y=0: t -> {qa, ka16, wtp}; y=1: x -> {qb, kb16, wxp}.
// q: Ah*Wq. k: Ah*Wk. message: Ah*Wm (single pass).
__global__ void __launch_bounds__(256, 2)
proj_mma_kernel(const float* __restrict__ x, const float* __restrict__ t,
                const float* __restrict__ Qa_b, const float* __restrict__ Ka_b,
                const float* __restrict__ Qb_b, const float* __restrict__ Kb_b, int N) {
    extern __shared__ __half sm[];
    uint32_t sm_base = (uint32_t)__cvta_generic_to_shared(sm);

    const int tid  = threadIdx.x;
    const int wid  = tid >> 5;
    const int lane = tid & 31;
    const int y    = blockIdx.y;
    const int row0 = blockIdx.x * 64;

    const float* in = y ? x : t;
    const float* Bias[2];
    Bias[0] = y ? Qb_b : Qa_b;
    Bias[1] = y ? Kb_b : Ka_b;
    float* dst_q = y ? g_qb : g_qa;
    __half* dst_w = y ? g_wxp : g_wtp;
    __nv_bfloat16* dst_k = y ? g_kb16 : g_ka16;
    const __half* wb = g_wh + (size_t)(y * 3) * (DD * DD);

    // ---- issue B0 <- W[0] ----
#pragma unroll
    for (int it = 0; it < 8; it++) {
        int c = tid + it * 256;
        int r = c >> 4, h8 = c & 15;
        uint32_t dst = sm_base + (uint32_t)((B0_OFF + r * ROWE + h8 * 8) * 2);
        cp_async16(dst, wb + (size_t)r * DD + h8 * 8);
    }
    CP_ASYNC_COMMIT();

    // ---- load A tile (64 x 128 fp32), convert to fp16 ----
#pragma unroll
    for (int it = 0; it < 8; it++) {
        int c = tid + it * 256;
        int r = c >> 5, q4 = c & 31;
        int gr = row0 + r;
        float4 v = make_float4(0.f, 0.f, 0.f, 0.f);
        if (gr < N) v = *(const float4*)(in + (size_t)gr * DD + q4 * 4);
        __half* ah = sm + AH_OFF + r * ROWE + q4 * 4;
        ah[0] = __float2half_rn(v.x);
        ah[1] = __float2half_rn(v.y);
        ah[2] = __float2half_rn(v.z);
        ah[3] = __float2half_rn(v.w);
    }
    CP_ASYNC_WAIT_ALL();
    __syncthreads();

    const int warpM = (wid >> 1) * 16;   // 0,16,32,48
    const int warpN = (wid & 1) * 64;    // 0,64
    const int g = lane >> 2;             // 0..7
    const int tg = lane & 3;             // 0..3
    const __half* Ahs = sm + AH_OFF;
    const __half* Bs0 = sm + B0_OFF;
    const __half* Bs1 = sm + B1_OFF;

    // ---- prefetch B1 <- W[1], compute q on B0 ----
#pragma unroll
    for (int it = 0; it < 8; it++) {
        int c = tid + it * 256;
        int r = c >> 4, h8 = c & 15;
        uint32_t dst = sm_base + (uint32_t)((B1_OFF + r * ROWE + h8 * 8) * 2);
        cp_async16(dst, wb + (size_t)DD * DD + (size_t)r * DD + h8 * 8);
    }
    CP_ASYNC_COMMIT();

    float acc[8][4];
#pragma unroll
    for (int fn = 0; fn < 8; fn++)
#pragma unroll
        for (int i = 0; i < 4; i++) acc[fn][i] = 0.f;
    gemm_pass(acc, Ahs, Bs0, warpM, warpN, g, tg);

    // epilogue q -> fp32 + bias
    {
        const float* bias = Bias[0];
        int m_lo = row0 + warpM + g, m_hi = m_lo + 8;
#pragma unroll
        for (int fn = 0; fn < 8; fn++) {
            int col = warpN + fn * 8 + 2 * tg;
            float2 bv = *(const float2*)(bias + col);
            if (m_lo < N)
                *(float2*)(dst_q + (size_t)m_lo * DD + col) =
                    make_float2(acc[fn][0] + bv.x, acc[fn][1] + bv.y);
            if (m_hi < N)
                *(float2*)(dst_q + (size_t)m_hi * DD + col) =
                    make_float2(acc[fn][2] + bv.x, acc[fn][3] + bv.y);
        }
    }
    CP_ASYNC_WAIT_ALL();
    __syncthreads();

    // ---- prefetch B0 <- W[2] (message weight), compute k on B1 ----
#pragma unroll
    for (int it = 0; it < 8; it++) {
        int c = tid + it * 256;
        int r = c >> 4, h8 = c & 15;
        uint32_t dst = sm_base + (uint32_t)((B0_OFF + r * ROWE + h8 * 8) * 2);
        cp_async16(dst, wb + (size_t)2 * DD * DD + (size_t)r * DD + h8 * 8);
    }
    CP_ASYNC_COMMIT();

#pragma unroll
    for (int fn = 0; fn < 8; fn++)
#pragma unroll
        for (int i = 0; i < 4; i++) acc[fn][i] = 0.f;
    gemm_pass(acc, Ahs, Bs1, warpM, warpN, g, tg);

    // epilogue k -> bf16 + bias
    {
        const float* bias = Bias[1];
        int m_lo = row0 + warpM + g, m_hi = m_lo + 8;
#pragma unroll
        for (int fn = 0; fn < 8; fn++) {
            int col = warpN + fn * 8 + 2 * tg;
            float2 bv = *(const float2*)(bias + col);
            if (m_lo < N) {
                __nv_bfloat162 h = __floats2bfloat162_rn(acc[fn][0] + bv.x,
                                                         acc[fn][1] + bv.y);
                *(unsigned int*)(dst_k + (size_t)m_lo * DD + col) = *(unsigned int*)&h;
            }
            if (m_hi < N) {
                __nv_bfloat162 h = __floats2bfloat162_rn(acc[fn][2] + bv.x,
                                                         acc[fn][3] + bv.y);
                *(unsigned int*)(dst_k + (size_t)m_hi * DD + col) = *(unsigned int*)&h;
            }
        }
    }
    CP_ASYNC_WAIT_ALL();
    __syncthreads();

    // ---- message GEMM: Ah*Wm on B0 (single pass) ----
#pragma unroll
    for (int fn = 0; fn < 8; fn++)
#pragma unroll
        for (int i = 0; i < 4; i++) acc[fn][i] = 0.f;
    gemm_pass(acc, Ahs, Bs0, warpM, warpN, g, tg);

    // epilogue message -> fp16, no bias
    {
        int m_lo = row0 + warpM + g, m_hi = m_lo + 8;
#pragma unroll
        for (int fn = 0; fn < 8; fn++) {
            int col = warpN + fn * 8 + 2 * tg;
            if (m_lo < N) {
                __half2 h = __floats2half2_rn(acc[fn][0], acc[fn][1]);
                *(unsigned int*)(dst_w + (size_t)m_lo * DD + col) = *(unsigned int*)&h;
            }
            if (m_hi < N) {
                __half2 h = __floats2half2_rn(acc[fn][2], acc[fn][3]);
                *(unsigned int*)(dst_w + (size_t)m_hi * DD + col) = *(unsigned int*)&h;
            }
        }
    }
}

// ---------------- CSR construction ----------------
__global__ void count_deg_kernel(const int* __restrict__ rows, int E) {
    int e = blockIdx.x * blockDim.x + threadIdx.x;
    if (e < E) atomicAdd(&g_deg[rows[e]], 1);
}

// scan1 also re-zeroes g_deg for the next call (arrays are zero-init at load)
__global__ void scan1_kernel(int N) {
    __shared__ int wsum[32];
    int tid = threadIdx.x, lane = tid & 31, wid = tid >> 5;
    int i = blockIdx.x * 1024 + tid;
    int v = 0;
    if (i < N) {
        v = g_deg[i];
        g_deg[i] = 0;
    }
    int s = v;
#pragma unroll
    for (int off = 1; off < 32; off <<= 1) {
        int u = __shfl_up_sync(0xffffffffu, s, off);
        if (lane >= off) s += u;
    }
    if (lane == 31) wsum[wid] = s;
    __syncthreads();
    if (wid == 0) {
        int ts = wsum[lane];
#pragma unroll
        for (int off = 1; off < 32; off <<= 1) {
            int u = __shfl_up_sync(0xffffffffu, ts, off);
            if (lane >= off) ts += u;
        }
        wsum[lane] = ts;
    }
    __syncthreads();
    int excl = (wid > 0 ? wsum[wid - 1] : 0) + (s - v);
    if (i < N) g_off[i] = excl;
    if (tid == 1023) g_bsum[blockIdx.x] = wsum[31];
}

// scan3 with inlined block-prefix: warp 0 sums g_bsum[0..blockIdx.x)
__global__ void scan3_kernel(int G, int N, int E) {
    __shared__ int pre_sh;
    int tid = threadIdx.x, lane = tid & 31, wid = tid >> 5;
    if (wid == 0) {
        int b = blockIdx.x;
        int v = 0;
        if (lane < b && lane < G) v += g_bsum[lane];
        if (32 + lane < b && 32 + lane < G) v += g_bsum[32 + lane];
#pragma unroll
        for (int off = 16; off > 0; off >>= 1)
            v += __shfl_xor_sync(0xffffffffu, v, off);
        if (lane == 0) pre_sh = v;
    }
    __syncthreads();
    int pre = pre_sh;
    int i = blockIdx.x * 1024 + tid;
    if (i < N) {
        int o = g_off[i] + pre;
        g_off[i] = o;
        g_cur[i] = o;
    }
    if (blockIdx.x == 0 && tid == 0) g_off[N] = E;
}

__global__ void scatter_kernel(const int* __restrict__ rows, const int* __restrict__ cols,
                               int E) {
    int e = blockIdx.x * blockDim.x + threadIdx.x;
    if (e < E) {
        int p = atomicAdd(&g_cur[rows[e]], 1);
        g_scol[p] = cols[e];
    }
}

// ---------------- fused scores + aggregation: one warp per dest node ----------------
__global__ void agg_kernel(float* __restrict__ out_x, float* __restrict__ out_t, int N) {
    int w    = blockIdx.x * (blockDim.x >> 5) + (threadIdx.x >> 5);
    int lane = threadIdx.x & 31;
    if (w >= N) return;
    int p0 = g_off[w];
    int p1 = g_off[w + 1];

    const float s = 0.08838834764831845f;  // 1/sqrt(128)
    float4 qa = *(const float4*)(g_qa + (size_t)w * DD + lane * 4);
    float4 qb = *(const float4*)(g_qb + (size_t)w * DD + lane * 4);
    qa.x *= s; qa.y *= s; qa.z *= s; qa.w *= s;
    qb.x *= s; qb.y *= s; qb.z *= s; qb.w *= s;

    float stx = 0.f, sty = 0.f, stz = 0.f, stw = 0.f;
    float sxx = 0.f, sxy = 0.f, sxz = 0.f, sxw = 0.f;
    float da = 0.f, db = 0.f;

    // depth-1 index prefetch: break the scol-load -> payload-address chain
    int j = (p0 < p1) ? g_scol[p0] : 0;
    for (int p = p0; p < p1; p++) {
        int j_next = (p + 1 < p1) ? g_scol[p + 1] : 0;
        uint2 kau = *(const uint2*)(g_ka16 + (size_t)j * DD + lane * 4);
        uint2 kbu = *(const uint2*)(g_kb16 + (size_t)j * DD + lane * 4);
        uint2 wtu = *(const uint2*)(g_wtp + (size_t)j * DD + lane * 4);
        uint2 wxu = *(const uint2*)(g_wxp + (size_t)j * DD + lane * 4);

        float2 ka0 = __bfloat1622float2(*(__nv_bfloat162*)&kau.x);
        float2 ka1 = __bfloat1622float2(*(__nv_bfloat162*)&kau.y);
        float2 kb0 = __bfloat1622float2(*(__nv_bfloat162*)&kbu.x);
        float2 kb1 = __bfloat1622float2(*(__nv_bfloat162*)&kbu.y);

        float sa = qa.x * ka0.x + qa.y * ka0.y + qa.z * ka1.x + qa.w * ka1.y;
        float sb = qb.x * kb0.x + qb.y * kb0.y + qb.z * kb1.x + qb.w * kb1.y;
#pragma unroll
        for (int off = 16; off > 0; off >>= 1) {
            sa += __shfl_xor_sync(0xffffffffu, sa, off);
            sb += __shfl_xor_sync(0xffffffffu, sb, off);
        }
        float ea = __expf(sa);
        float eb = __expf(sb);

        float2 wt0 = __half22float2(*(__half2*)&wtu.x);
        float2 wt1 = __half22float2(*(__half2*)&wtu.y);
        float2 wx0 = __half22float2(*(__half2*)&wxu.x);
        float2 wx1 = __half22float2(*(__half2*)&wxu.y);

        stx = fmaf(ea, wt0.x, stx);
        sty = fmaf(ea, wt0.y, sty);
        stz = fmaf(ea, wt1.x, stz);
        stw = fmaf(ea, wt1.y, stw);
        sxx = fmaf(eb, wx0.x, sxx);
        sxy = fmaf(eb, wx0.y, sxy);
        sxz = fmaf(eb, wx1.x, sxz);
        sxw = fmaf(eb, wx1.y, sxw);
        da += ea;
        db += eb;
        j = j_next;
    }
    float ia = (da > 0.f) ? 1.f / da : 0.f;
    float ib = (db > 0.f) ? 1.f / db : 0.f;
    *(float4*)(out_t + (size_t)w * DD + lane * 4) =
        make_float4(stx * ia, sty * ia, stz * ia, stw * ia);
    *(float4*)(out_x + (size_t)w * DD + lane * 4) =
        make_float4(sxx * ib, sxy * ib, sxz * ib, sxw * ib);
}

// ---------------- launch (fork-join: CSR chain overlaps proj GEMMs) ----------------
static cudaStream_t g_s2 = nullptr;
static cudaEvent_t g_ev0 = nullptr, g_ev1 = nullptr;
static bool g_init_done = false;
static bool g_overlap_ok = false;

extern "C" void kernel_launch(void* const* d_in, const int* in_sizes, int n_in,
                              void* d_out, int out_size) {
    const float* x    = (const float*)d_in[0];
    const float* t    = (const float*)d_in[1];
    const int*   ei   = (const int*)d_in[2];
    const float* W_x  = (const float*)d_in[3];
    const float* W_t  = (const float*)d_in[4];
    const float* Qa_w = (const float*)d_in[5];
    const float* Qa_b = (const float*)d_in[6];
    const float* Ka_w = (const float*)d_in[7];
    const float* Ka_b = (const float*)d_in[8];
    const float* Qb_w = (const float*)d_in[9];
    const float* Qb_b = (const float*)d_in[10];
    const float* Kb_w = (const float*)d_in[11];
    const float* Kb_b = (const float*)d_in[12];

    const int N = in_sizes[0] / DD;
    const int E = in_sizes[2] / 2;
    const int* rows = ei;
    const int* cols = ei + E;

    float* out_x = (float*)d_out;
    float* out_t = out_x + (size_t)N * DD;

    const int G = (N + 1023) / 1024;

    if (!g_init_done) {
        g_init_done = true;
        bool ok = (cudaStreamCreateWithFlags(&g_s2, cudaStreamNonBlocking) == cudaSuccess);
        ok = ok && (cudaEventCreateWithFlags(&g_ev0, cudaEventDisableTiming) == cudaSuccess);
        ok = ok && (cudaEventCreateWithFlags(&g_ev1, cudaEventDisableTiming) == cudaSuccess);
        g_overlap_ok = ok;
    }

    cudaFuncSetAttribute(proj_mma_kernel, cudaFuncAttributeMaxDynamicSharedMemorySize,
                         SMEM_BYTES);
    dim3 pg((N + 63) / 64, 2);

    if (g_overlap_ok) {
        // fork: CSR chain on g_s2, weights+proj on the main stream
        cudaEventRecord(g_ev0, 0);
        cudaStreamWaitEvent(g_s2, g_ev0, 0);

        count_deg_kernel<<<(E + 255) / 256, 256, 0, g_s2>>>(rows, E);
        scan1_kernel<<<G, 1024, 0, g_s2>>>(N);
        scan3_kernel<<<G, 1024, 0, g_s2>>>(G, N, E);
        scatter_kernel<<<(E + 255) / 256, 256, 0, g_s2>>>(rows, cols, E);
        cudaEventRecord(g_ev1, g_s2);

        // weight order: 0=Qa, 1=Ka, 2=W_t, 3=Qb, 4=Kb, 5=W_x
        wsplit_kernel<<<6, 256>>>(Qa_w, Ka_w, W_t, Qb_w, Kb_w, W_x);
        proj_mma_kernel<<<pg, 256, SMEM_BYTES>>>(x, t, Qa_b, Ka_b, Qb_b, Kb_b, N);

        // join: agg needs both proj (program order) and CSR (event)
        cudaStreamWaitEvent(0, g_ev1, 0);
        agg_kernel<<<(N + 7) / 8, 256>>>(out_x, out_t, N);
    } else {
        wsplit_kernel<<<6, 256>>>(Qa_w, Ka_w, W_t, Qb_w, Kb_w, W_x);
        count_deg_kernel<<<(E + 255) / 256, 256>>>(rows, E);
        scan1_kernel<<<G, 1024>>>(N);
        scan3_kernel<<<G, 1024>>>(G, N, E);
        scatter_kernel<<<(E + 255) / 256, 256>>>(rows, cols, E);
        proj_mma_kernel<<<pg, 256, SMEM_BYTES>>>(x, t, Qa_b, Ka_b, Qb_b, Kb_b, N);
        agg_kernel<<<(N + 7) / 8, 256>>>(out_x, out_t, N);
    }
}

// round 15
// speedup vs baseline: 1.5126x; 1.0875x over previous
#include <cuda_runtime.h>
#include <cuda_bf16.h>
#include <cuda_fp16.h>
#include <stdint.h>
#include <stddef.h>

#define DD 128
#define NMAX 50176
#define EMAX 409600

// ---------------- device scratch ----------------
__device__ float g_qa[NMAX * DD];
__device__ float g_qb[NMAX * DD];
__device__ __half g_wtp[NMAX * DD];     // fp16 messages
__device__ __half g_wxp[NMAX * DD];
__device__ __nv_bfloat16 g_ka16[NMAX * DD];
__device__ __nv_bfloat16 g_kb16[NMAX * DD];
__device__ __half g_wh[6 * DD * DD];    // fp16-rounded weights
__device__ int   g_deg[NMAX];           // zero-init at load; re-zeroed by scan1
__device__ int   g_off[NMAX + 1];
__device__ int   g_cur[NMAX];
__device__ int   g_scol[EMAX];
__device__ int   g_bsum[64];

// ---------------- cp.async helpers (portable, Ampere+) ----------------
__device__ __forceinline__ void cp_async16(uint32_t dst_smem, const void* src) {
    asm volatile("cp.async.cg.shared.global [%0], [%1], 16;" ::
                 "r"(dst_smem), "l"(src) : "memory");
}
#define CP_ASYNC_COMMIT() asm volatile("cp.async.commit_group;" ::: "memory")
#define CP_ASYNC_WAIT_ALL() asm volatile("cp.async.wait_group 0;" ::: "memory")

// ---------------- fp16 warp MMA (m16n8k16) ----------------
__device__ __forceinline__ void mma_f16(float* c, uint32_t a0, uint32_t a1,
                                        uint32_t a2, uint32_t a3,
                                        uint32_t b0, uint32_t b1) {
    asm volatile(
        "mma.sync.aligned.m16n8k16.row.col.f32.f16.f16.f32 "
        "{%0,%1,%2,%3}, {%4,%5,%6,%7}, {%8,%9}, {%0,%1,%2,%3};"
        : "+f"(c[0]), "+f"(c[1]), "+f"(c[2]), "+f"(c[3])
        : "r"(a0), "r"(a1), "r"(a2), "r"(a3), "r"(b0), "r"(b1));
}

// smem layout (fp16 elems): A[128][136], B0[128][136], B1[128][136]
#define ROWE 136
#define AH_OFF 0
#define B0_OFF (128 * ROWE)
#define B1_OFF (B0_OFF + 128 * ROWE)
#define SMEM_ELEMS (B1_OFF + 128 * ROWE)
#define SMEM_BYTES (SMEM_ELEMS * 2)

// ---------------- weight fp16 round ----------------
__global__ void wsplit_kernel(const float* __restrict__ W0,
                              const float* __restrict__ W1,
                              const float* __restrict__ W2,
                              const float* __restrict__ W3,
                              const float* __restrict__ W4,
                              const float* __restrict__ W5) {
    const float* W;
    switch (blockIdx.x) {
        case 0: W = W0; break;
        case 1: W = W1; break;
        case 2: W = W2; break;
        case 3: W = W3; break;
        case 4: W = W4; break;
        default: W = W5; break;
    }
    __half* dst = g_wh + blockIdx.x * (DD * DD);
    for (int i = threadIdx.x; i < DD * DD; i += 256)
        dst[i] = __float2half_rn(W[i]);
}

// ---------------- GEMM inner pass: acc[2] += A(2x16 rows) @ B(64 cols)^T ----------------
// B loads shared across the two row-fragments (key amortization win).
__device__ __forceinline__ void gemm_pass2(float acc[2][8][4], const __half* Abase,
                                           const __half* Bbase, int warpM,
                                           int warpN, int g, int tg) {
    const __half* Ap0 = Abase + (warpM + g) * ROWE + 2 * tg;
    const __half* Ap1 = Ap0 + 16 * ROWE;
    const __half* Bp = Bbase + (warpN + g) * ROWE + 2 * tg;
#pragma unroll
    for (int ks = 0; ks < 8; ks++) {
        const int k0 = ks * 16;
        uint32_t a0[4], a1[4];
        a0[0] = *(const uint32_t*)(Ap0 + k0);
        a0[1] = *(const uint32_t*)(Ap0 + 8 * ROWE + k0);
        a0[2] = *(const uint32_t*)(Ap0 + k0 + 8);
        a0[3] = *(const uint32_t*)(Ap0 + 8 * ROWE + k0 + 8);
        a1[0] = *(const uint32_t*)(Ap1 + k0);
        a1[1] = *(const uint32_t*)(Ap1 + 8 * ROWE + k0);
        a1[2] = *(const uint32_t*)(Ap1 + k0 + 8);
        a1[3] = *(const uint32_t*)(Ap1 + 8 * ROWE + k0 + 8);
#pragma unroll
        for (int fn = 0; fn < 8; fn++) {
            const __half* bp = Bp + fn * 8 * ROWE + k0;
            uint32_t b0 = *(const uint32_t*)bp;
            uint32_t b1 = *(const uint32_t*)(bp + 8);
            mma_f16(acc[0][fn], a0[0], a0[1], a0[2], a0[3], b0, b1);
            mma_f16(acc[1][fn], a1[0], a1[1], a1[2], a1[3], b0, b1);
        }
    }
}

// ---------------- fused fp16 projection GEMM (128-row tiles) ----------------
// grid (ceil(N/128), 2). y=0: t -> {qa, ka16, wtp}; y=1: x -> {qb, kb16, wxp}.
__global__ void __launch_bounds__(256, 2)
proj_mma_kernel(const float* __restrict__ x, const float* __restrict__ t,
                const float* __restrict__ Qa_b, const float* __restrict__ Ka_b,
                const float* __restrict__ Qb_b, const float* __restrict__ Kb_b, int N) {
    extern __shared__ __half sm[];
    uint32_t sm_base = (uint32_t)__cvta_generic_to_shared(sm);

    const int tid  = threadIdx.x;
    const int wid  = tid >> 5;
    const int lane = tid & 31;
    const int y    = blockIdx.y;
    const int row0 = blockIdx.x * 128;

    const float* in = y ? x : t;
    const float* Bias[2];
    Bias[0] = y ? Qb_b : Qa_b;
    Bias[1] = y ? Kb_b : Ka_b;
    float* dst_q = y ? g_qb : g_qa;
    __half* dst_w = y ? g_wxp : g_wtp;
    __nv_bfloat16* dst_k = y ? g_kb16 : g_ka16;
    const __half* wb = g_wh + (size_t)(y * 3) * (DD * DD);

    // ---- issue B0 <- W[0] ----
#pragma unroll
    for (int it = 0; it < 8; it++) {
        int c = tid + it * 256;
        int r = c >> 4, h8 = c & 15;
        uint32_t dst = sm_base + (uint32_t)((B0_OFF + r * ROWE + h8 * 8) * 2);
        cp_async16(dst, wb + (size_t)r * DD + h8 * 8);
    }
    CP_ASYNC_COMMIT();

    // ---- load A tile (128 x 128 fp32), convert to fp16 ----
#pragma unroll
    for (int it = 0; it < 16; it++) {
        int c = tid + it * 256;
        int r = c >> 5, q4 = c & 31;
        int gr = row0 + r;
        float4 v = make_float4(0.f, 0.f, 0.f, 0.f);
        if (gr < N) v = *(const float4*)(in + (size_t)gr * DD + q4 * 4);
        __half* ah = sm + AH_OFF + r * ROWE + q4 * 4;
        ah[0] = __float2half_rn(v.x);
        ah[1] = __float2half_rn(v.y);
        ah[2] = __float2half_rn(v.z);
        ah[3] = __float2half_rn(v.w);
    }
    CP_ASYNC_WAIT_ALL();
    __syncthreads();

    const int warpM = (wid >> 1) * 32;   // 0,32,64,96
    const int warpN = (wid & 1) * 64;    // 0,64
    const int g = lane >> 2;             // 0..7
    const int tg = lane & 3;             // 0..3
    const __half* Ahs = sm + AH_OFF;
    const __half* Bs0 = sm + B0_OFF;
    const __half* Bs1 = sm + B1_OFF;

    // ---- prefetch B1 <- W[1], compute q on B0 ----
#pragma unroll
    for (int it = 0; it < 8; it++) {
        int c = tid + it * 256;
        int r = c >> 4, h8 = c & 15;
        uint32_t dst = sm_base + (uint32_t)((B1_OFF + r * ROWE + h8 * 8) * 2);
        cp_async16(dst, wb + (size_t)DD * DD + (size_t)r * DD + h8 * 8);
    }
    CP_ASYNC_COMMIT();

    float acc[2][8][4];
#pragma unroll
    for (int fm = 0; fm < 2; fm++)
#pragma unroll
        for (int fn = 0; fn < 8; fn++)
#pragma unroll
            for (int i = 0; i < 4; i++) acc[fm][fn][i] = 0.f;
    gemm_pass2(acc, Ahs, Bs0, warpM, warpN, g, tg);

    // epilogue q -> fp32 + bias
    {
        const float* bias = Bias[0];
#pragma unroll
        for (int fm = 0; fm < 2; fm++) {
            int m_lo = row0 + warpM + fm * 16 + g, m_hi = m_lo + 8;
#pragma unroll
            for (int fn = 0; fn < 8; fn++) {
                int col = warpN + fn * 8 + 2 * tg;
                float2 bv = *(const float2*)(bias + col);
                if (m_lo < N)
                    *(float2*)(dst_q + (size_t)m_lo * DD + col) =
                        make_float2(acc[fm][fn][0] + bv.x, acc[fm][fn][1] + bv.y);
                if (m_hi < N)
                    *(float2*)(dst_q + (size_t)m_hi * DD + col) =
                        make_float2(acc[fm][fn][2] + bv.x, acc[fm][fn][3] + bv.y);
            }
        }
    }
    CP_ASYNC_WAIT_ALL();
    __syncthreads();

    // ---- prefetch B0 <- W[2] (message weight), compute k on B1 ----
#pragma unroll
    for (int it = 0; it < 8; it++) {
        int c = tid + it * 256;
        int r = c >> 4, h8 = c & 15;
        uint32_t dst = sm_base + (uint32_t)((B0_OFF + r * ROWE + h8 * 8) * 2);
        cp_async16(dst, wb + (size_t)2 * DD * DD + (size_t)r * DD + h8 * 8);
    }
    CP_ASYNC_COMMIT();

#pragma unroll
    for (int fm = 0; fm < 2; fm++)
#pragma unroll
        for (int fn = 0; fn < 8; fn++)
#pragma unroll
            for (int i = 0; i < 4; i++) acc[fm][fn][i] = 0.f;
    gemm_pass2(acc, Ahs, Bs1, warpM, warpN, g, tg);

    // epilogue k -> bf16 + bias
    {
        const float* bias = Bias[1];
#pragma unroll
        for (int fm = 0; fm < 2; fm++) {
            int m_lo = row0 + warpM + fm * 16 + g, m_hi = m_lo + 8;
#pragma unroll
            for (int fn = 0; fn < 8; fn++) {
                int col = warpN + fn * 8 + 2 * tg;
                float2 bv = *(const float2*)(bias + col);
                if (m_lo < N) {
                    __nv_bfloat162 h = __floats2bfloat162_rn(acc[fm][fn][0] + bv.x,
                                                             acc[fm][fn][1] + bv.y);
                    *(unsigned int*)(dst_k + (size_t)m_lo * DD + col) =
                        *(unsigned int*)&h;
                }
                if (m_hi < N) {
                    __nv_bfloat162 h = __floats2bfloat162_rn(acc[fm][fn][2] + bv.x,
                                                             acc[fm][fn][3] + bv.y);
                    *(unsigned int*)(dst_k + (size_t)m_hi * DD + col) =
                        *(unsigned int*)&h;
                }
            }
        }
    }
    CP_ASYNC_WAIT_ALL();
    __syncthreads();

    // ---- message GEMM: A*Wm on B0 (single pass) ----
#pragma unroll
    for (int fm = 0; fm < 2; fm++)
#pragma unroll
        for (int fn = 0; fn < 8; fn++)
#pragma unroll
            for (int i = 0; i < 4; i++) acc[fm][fn][i] = 0.f;
    gemm_pass2(acc, Ahs, Bs0, warpM, warpN, g, tg);

    // epilogue message -> fp16, no bias
    {
#pragma unroll
        for (int fm = 0; fm < 2; fm++) {
            int m_lo = row0 + warpM + fm * 16 + g, m_hi = m_lo + 8;
#pragma unroll
            for (int fn = 0; fn < 8; fn++) {
                int col = warpN + fn * 8 + 2 * tg;
                if (m_lo < N) {
                    __half2 h = __floats2half2_rn(acc[fm][fn][0], acc[fm][fn][1]);
                    *(unsigned int*)(dst_w + (size_t)m_lo * DD + col) =
                        *(unsigned int*)&h;
                }
                if (m_hi < N) {
                    __half2 h = __floats2half2_rn(acc[fm][fn][2], acc[fm][fn][3]);
                    *(unsigned int*)(dst_w + (size_t)m_hi * DD + col) =
                        *(unsigned int*)&h;
                }
            }
        }
    }
}

// ---------------- CSR construction ----------------
__global__ void count_deg_kernel(const int* __restrict__ rows, int E) {
    int e = blockIdx.x * blockDim.x + threadIdx.x;
    if (e < E) atomicAdd(&g_deg[rows[e]], 1);
}

// scan1 also re-zeroes g_deg for the next call (arrays are zero-init at load)
__global__ void scan1_kernel(int N) {
    __shared__ int wsum[32];
    int tid = threadIdx.x, lane = tid & 31, wid = tid >> 5;
    int i = blockIdx.x * 1024 + tid;
    int v = 0;
    if (i < N) {
        v = g_deg[i];
        g_deg[i] = 0;
    }
    int s = v;
#pragma unroll
    for (int off = 1; off < 32; off <<= 1) {
        int u = __shfl_up_sync(0xffffffffu, s, off);
        if (lane >= off) s += u;
    }
    if (lane == 31) wsum[wid] = s;
    __syncthreads();
    if (wid == 0) {
        int ts = wsum[lane];
#pragma unroll
        for (int off = 1; off < 32; off <<= 1) {
            int u = __shfl_up_sync(0xffffffffu, ts, off);
            if (lane >= off) ts += u;
        }
        wsum[lane] = ts;
    }
    __syncthreads();
    int excl = (wid > 0 ? wsum[wid - 1] : 0) + (s - v);
    if (i < N) g_off[i] = excl;
    if (tid == 1023) g_bsum[blockIdx.x] = wsum[31];
}

// scan3 with inlined block-prefix: warp 0 sums g_bsum[0..blockIdx.x)
__global__ void scan3_kernel(int G, int N, int E) {
    __shared__ int pre_sh;
    int tid = threadIdx.x, lane = tid & 31, wid = tid >> 5;
    if (wid == 0) {
        int b = blockIdx.x;
        int v = 0;
        if (lane < b && lane < G) v += g_bsum[lane];
        if (32 + lane < b && 32 + lane < G) v += g_bsum[32 + lane];
#pragma unroll
        for (int off = 16; off > 0; off >>= 1)
            v += __shfl_xor_sync(0xffffffffu, v, off);
        if (lane == 0) pre_sh = v;
    }
    __syncthreads();
    int pre = pre_sh;
    int i = blockIdx.x * 1024 + tid;
    if (i < N) {
        int o = g_off[i] + pre;
        g_off[i] = o;
        g_cur[i] = o;
    }
    if (blockIdx.x == 0 && tid == 0) g_off[N] = E;
}

__global__ void scatter_kernel(const int* __restrict__ rows, const int* __restrict__ cols,
                               int E) {
    int e = blockIdx.x * blockDim.x + threadIdx.x;
    if (e < E) {
        int p = atomicAdd(&g_cur[rows[e]], 1);
        g_scol[p] = cols[e];
    }
}

// ---------------- fused scores + aggregation: one warp per dest node ----------------
__global__ void agg_kernel(float* __restrict__ out_x, float* __restrict__ out_t, int N) {
    int w    = blockIdx.x * (blockDim.x >> 5) + (threadIdx.x >> 5);
    int lane = threadIdx.x & 31;
    if (w >= N) return;
    int p0 = g_off[w];
    int p1 = g_off[w + 1];

    const float s = 0.08838834764831845f;  // 1/sqrt(128)
    float4 qa = *(const float4*)(g_qa + (size_t)w * DD + lane * 4);
    float4 qb = *(const float4*)(g_qb + (size_t)w * DD + lane * 4);
    qa.x *= s; qa.y *= s; qa.z *= s; qa.w *= s;
    qb.x *= s; qb.y *= s; qb.z *= s; qb.w *= s;

    float stx = 0.f, sty = 0.f, stz = 0.f, stw = 0.f;
    float sxx = 0.f, sxy = 0.f, sxz = 0.f, sxw = 0.f;
    float da = 0.f, db = 0.f;

    int p = p0;
    for (; p + 1 < p1; p += 2) {
        int j0 = g_scol[p];
        int j1 = g_scol[p + 1];
        // issue all 8 gathers up front (max MLP)
        uint2 kau0 = *(const uint2*)(g_ka16 + (size_t)j0 * DD + lane * 4);
        uint2 kbu0 = *(const uint2*)(g_kb16 + (size_t)j0 * DD + lane * 4);
        uint2 wtu0 = *(const uint2*)(g_wtp + (size_t)j0 * DD + lane * 4);
        uint2 wxu0 = *(const uint2*)(g_wxp + (size_t)j0 * DD + lane * 4);
        uint2 kau1 = *(const uint2*)(g_ka16 + (size_t)j1 * DD + lane * 4);
        uint2 kbu1 = *(const uint2*)(g_kb16 + (size_t)j1 * DD + lane * 4);
        uint2 wtu1 = *(const uint2*)(g_wtp + (size_t)j1 * DD + lane * 4);
        uint2 wxu1 = *(const uint2*)(g_wxp + (size_t)j1 * DD + lane * 4);

        float2 a00 = __bfloat1622float2(*(__nv_bfloat162*)&kau0.x);
        float2 a01 = __bfloat1622float2(*(__nv_bfloat162*)&kau0.y);
        float2 b00 = __bfloat1622float2(*(__nv_bfloat162*)&kbu0.x);
        float2 b01 = __bfloat1622float2(*(__nv_bfloat162*)&kbu0.y);
        float2 a10 = __bfloat1622float2(*(__nv_bfloat162*)&kau1.x);
        float2 a11 = __bfloat1622float2(*(__nv_bfloat162*)&kau1.y);
        float2 b10 = __bfloat1622float2(*(__nv_bfloat162*)&kbu1.x);
        float2 b11 = __bfloat1622float2(*(__nv_bfloat162*)&kbu1.y);

        float sa0 = qa.x * a00.x + qa.y * a00.y + qa.z * a01.x + qa.w * a01.y;
        float sb0 = qb.x * b00.x + qb.y * b00.y + qb.z * b01.x + qb.w * b01.y;
        float sa1 = qa.x * a10.x + qa.y * a10.y + qa.z * a11.x + qa.w * a11.y;
        float sb1 = qb.x * b10.x + qb.y * b10.y + qb.z * b11.x + qb.w * b11.y;
#pragma unroll
        for (int off = 16; off > 0; off >>= 1) {
            sa0 += __shfl_xor_sync(0xffffffffu, sa0, off);
            sb0 += __shfl_xor_sync(0xffffffffu, sb0, off);
            sa1 += __shfl_xor_sync(0xffffffffu, sa1, off);
            sb1 += __shfl_xor_sync(0xffffffffu, sb1, off);
        }
        float ea0 = __expf(sa0), eb0 = __expf(sb0);
        float ea1 = __expf(sa1), eb1 = __expf(sb1);

        float2 wt00 = __half22float2(*(__half2*)&wtu0.x);
        float2 wt01 = __half22float2(*(__half2*)&wtu0.y);
        float2 wx00 = __half22float2(*(__half2*)&wxu0.x);
        float2 wx01 = __half22float2(*(__half2*)&wxu0.y);
        float2 wt10 = __half22float2(*(__half2*)&wtu1.x);
        float2 wt11 = __half22float2(*(__half2*)&wtu1.y);
        float2 wx10 = __half22float2(*(__half2*)&wxu1.x);
        float2 wx11 = __half22float2(*(__half2*)&wxu1.y);

        stx = fmaf(ea0, wt00.x, fmaf(ea1, wt10.x, stx));
        sty = fmaf(ea0, wt00.y, fmaf(ea1, wt10.y, sty));
        stz = fmaf(ea0, wt01.x, fmaf(ea1, wt11.x, stz));
        stw = fmaf(ea0, wt01.y, fmaf(ea1, wt11.y, stw));
        sxx = fmaf(eb0, wx00.x, fmaf(eb1, wx10.x, sxx));
        sxy = fmaf(eb0, wx00.y, fmaf(eb1, wx10.y, sxy));
        sxz = fmaf(eb0, wx01.x, fmaf(eb1, wx11.x, sxz));
        sxw = fmaf(eb0, wx01.y, fmaf(eb1, wx11.y, sxw));
        da += ea0 + ea1;
        db += eb0 + eb1;
    }
    if (p < p1) {
        int j = g_scol[p];
        uint2 kau = *(const uint2*)(g_ka16 + (size_t)j * DD + lane * 4);
        uint2 kbu = *(const uint2*)(g_kb16 + (size_t)j * DD + lane * 4);
        uint2 wtu = *(const uint2*)(g_wtp + (size_t)j * DD + lane * 4);
        uint2 wxu = *(const uint2*)(g_wxp + (size_t)j * DD + lane * 4);

        float2 ka0 = __bfloat1622float2(*(__nv_bfloat162*)&kau.x);
        float2 ka1 = __bfloat1622float2(*(__nv_bfloat162*)&kau.y);
        float2 kb0 = __bfloat1622float2(*(__nv_bfloat162*)&kbu.x);
        float2 kb1 = __bfloat1622float2(*(__nv_bfloat162*)&kbu.y);

        float sa = qa.x * ka0.x + qa.y * ka0.y + qa.z * ka1.x + qa.w * ka1.y;
        float sb = qb.x * kb0.x + qb.y * kb0.y + qb.z * kb1.x + qb.w * kb1.y;
#pragma unroll
        for (int off = 16; off > 0; off >>= 1) {
            sa += __shfl_xor_sync(0xffffffffu, sa, off);
            sb += __shfl_xor_sync(0xffffffffu, sb, off);
        }
        float ea = __expf(sa), eb = __expf(sb);

        float2 wt0 = __half22float2(*(__half2*)&wtu.x);
        float2 wt1 = __half22float2(*(__half2*)&wtu.y);
        float2 wx0 = __half22float2(*(__half2*)&wxu.x);
        float2 wx1 = __half22float2(*(__half2*)&wxu.y);

        stx = fmaf(ea, wt0.x, stx);
        sty = fmaf(ea, wt0.y, sty);
        stz = fmaf(ea, wt1.x, stz);
        stw = fmaf(ea, wt1.y, stw);
        sxx = fmaf(eb, wx0.x, sxx);
        sxy = fmaf(eb, wx0.y, sxy);
        sxz = fmaf(eb, wx1.x, sxz);
        sxw = fmaf(eb, wx1.y, sxw);
        da += ea;
        db += eb;
    }
    float ia = (da > 0.f) ? 1.f / da : 0.f;
    float ib = (db > 0.f) ? 1.f / db : 0.f;
    *(float4*)(out_t + (size_t)w * DD + lane * 4) =
        make_float4(stx * ia, sty * ia, stz * ia, stw * ia);
    *(float4*)(out_x + (size_t)w * DD + lane * 4) =
        make_float4(sxx * ib, sxy * ib, sxz * ib, sxw * ib);
}

// ---------------- launch (fork-join: CSR chain overlaps proj GEMMs) ----------------
static cudaStream_t g_s2 = nullptr;
static cudaEvent_t g_ev0 = nullptr, g_ev1 = nullptr;
static bool g_init_done = false;
static bool g_overlap_ok = false;

extern "C" void kernel_launch(void* const* d_in, const int* in_sizes, int n_in,
                              void* d_out, int out_size) {
    const float* x    = (const float*)d_in[0];
    const float* t    = (const float*)d_in[1];
    const int*   ei   = (const int*)d_in[2];
    const float* W_x  = (const float*)d_in[3];
    const float* W_t  = (const float*)d_in[4];
    const float* Qa_w = (const float*)d_in[5];
    const float* Qa_b = (const float*)d_in[6];
    const float* Ka_w = (const float*)d_in[7];
    const float* Ka_b = (const float*)d_in[8];
    const float* Qb_w = (const float*)d_in[9];
    const float* Qb_b = (const float*)d_in[10];
    const float* Kb_w = (const float*)d_in[11];
    const float* Kb_b = (const float*)d_in[12];

    const int N = in_sizes[0] / DD;
    const int E = in_sizes[2] / 2;
    const int* rows = ei;
    const int* cols = ei + E;

    float* out_x = (float*)d_out;
    float* out_t = out_x + (size_t)N * DD;

    const int G = (N + 1023) / 1024;

    if (!g_init_done) {
        g_init_done = true;
        bool ok = (cudaStreamCreateWithFlags(&g_s2, cudaStreamNonBlocking) == cudaSuccess);
        ok = ok && (cudaEventCreateWithFlags(&g_ev0, cudaEventDisableTiming) == cudaSuccess);
        ok = ok && (cudaEventCreateWithFlags(&g_ev1, cudaEventDisableTiming) == cudaSuccess);
        g_overlap_ok = ok;
    }

    cudaFuncSetAttribute(proj_mma_kernel, cudaFuncAttributeMaxDynamicSharedMemorySize,
                         SMEM_BYTES);
    dim3 pg((N + 127) / 128, 2);

    if (g_overlap_ok) {
        // fork: CSR chain on g_s2, weights+proj on the main stream
        cudaEventRecord(g_ev0, 0);
        cudaStreamWaitEvent(g_s2, g_ev0, 0);

        count_deg_kernel<<<(E + 255) / 256, 256, 0, g_s2>>>(rows, E);
        scan1_kernel<<<G, 1024, 0, g_s2>>>(N);
        scan3_kernel<<<G, 1024, 0, g_s2>>>(G, N, E);
        scatter_kernel<<<(E + 255) / 256, 256, 0, g_s2>>>(rows, cols, E);
        cudaEventRecord(g_ev1, g_s2);

        // weight order: 0=Qa, 1=Ka, 2=W_t, 3=Qb, 4=Kb, 5=W_x
        wsplit_kernel<<<6, 256>>>(Qa_w, Ka_w, W_t, Qb_w, Kb_w, W_x);
        proj_mma_kernel<<<pg, 256, SMEM_BYTES>>>(x, t, Qa_b, Ka_b, Qb_b, Kb_b, N);

        // join: agg needs both proj (program order) and CSR (event)
        cudaStreamWaitEvent(0, g_ev1, 0);
        agg_kernel<<<(N + 7) / 8, 256>>>(out_x, out_t, N);
    } else {
        wsplit_kernel<<<6, 256>>>(Qa_w, Ka_w, W_t, Qb_w, Kb_w, W_x);
        count_deg_kernel<<<(E + 255) / 256, 256>>>(rows, E);
        scan1_kernel<<<G, 1024>>>(N);
        scan3_kernel<<<G, 1024>>>(G, N, E);
        scatter_kernel<<<(E + 255) / 256, 256>>>(rows, cols, E);
        proj_mma_kernel<<<pg, 256, SMEM_BYTES>>>(x, t, Qa_b, Ka_b, Qb_b, Kb_b, N);
        agg_kernel<<<(N + 7) / 8, 256>>>(out_x, out_t, N);
    }
}